// round 13
// baseline (speedup 1.0000x reference)
#include <cuda_runtime.h>
#include <cstdint>

#define BB 8
#define SS 1024
#define DD 1024
#define HH 16
#define HD 64

// Scratch (device globals). All contents tf32-rounded fp32 (rounded once, rna).
__device__ float g_Q[BB*HH*SS*HD];
__device__ float g_K[BB*HH*SS*HD];
__device__ float g_V[BB*HH*SS*HD];
__device__ float g_C[(size_t)BB*SS*DD];
__device__ float g_Wo[DD*DD];
__device__ float g_Wt[HH*3*HD*HD];   // [h][w][e][d] transposed+rounded QKV weights
__device__ int   g_idx[BB*SS];       // per-batch compacted unmasked key indices
__device__ int   g_nb[BB];           // per-batch unmasked count

// ---------------- helpers ----------------
static __device__ __forceinline__ uint32_t cvt_tf32(float f) {
    uint32_t u; asm("cvt.rna.tf32.f32 %0, %1;" : "=r"(u) : "f"(f)); return u;
}
static __device__ __forceinline__ float cvtf(float f) { return __uint_as_float(cvt_tf32(f)); }
static __device__ __forceinline__ float ex2f(float x) {
    float y; asm("ex2.approx.f32 %0, %1;" : "=f"(y) : "f"(x)); return y;
}
static __device__ __forceinline__ void mma8(float* d, const uint32_t* a, const uint32_t* b) {
    asm volatile("mma.sync.aligned.m16n8k8.row.col.f32.tf32.tf32.f32 "
        "{%0,%1,%2,%3}, {%4,%5,%6,%7}, {%8,%9}, {%0,%1,%2,%3};"
        : "+f"(d[0]), "+f"(d[1]), "+f"(d[2]), "+f"(d[3])
        : "r"(a[0]), "r"(a[1]), "r"(a[2]), "r"(a[3]), "r"(b[0]), "r"(b[1]));
}
static __device__ __forceinline__ void lda(uint32_t* a, const float* s, int P,
                                           int r0, int k0, int g, int t) {
    a[0] = __float_as_uint(s[(r0 + g) * P + k0 + t]);
    a[1] = __float_as_uint(s[(r0 + g + 8) * P + k0 + t]);
    a[2] = __float_as_uint(s[(r0 + g) * P + k0 + t + 4]);
    a[3] = __float_as_uint(s[(r0 + g + 8) * P + k0 + t + 4]);
}
static __device__ __forceinline__ void ldb_nk(uint32_t* b, const float* s, int P,
                                              int n0, int k0, int g, int t) {
    b[0] = __float_as_uint(s[(n0 + g) * P + k0 + t]);
    b[1] = __float_as_uint(s[(n0 + g) * P + k0 + t + 4]);
}
static __device__ __forceinline__ uint32_t smem_u32(const void* p) {
    uint32_t a;
    asm("{ .reg .u64 t; cvta.to.shared.u64 t, %1; cvt.u32.u64 %0, t; }" : "=r"(a) : "l"(p));
    return a;
}
static __device__ __forceinline__ void cpa16(uint32_t dst, const void* src) {
    asm volatile("cp.async.ca.shared.global [%0], [%1], 16;" :: "r"(dst), "l"(src));
}
#define CP_COMMIT() asm volatile("cp.async.commit_group;" ::: "memory")
#define CP_WAIT(n)  asm volatile("cp.async.wait_group %0;" :: "n"(n) : "memory")

// ============================================================================
// Kernel 0a: tf32-round Wo (once).
// ============================================================================
__global__ void round_wo(const float* __restrict__ Wo) {
    int i = (blockIdx.x * 256 + threadIdx.x) * 4;
    float4 v = *(const float4*)&Wo[i];
    *(float4*)&g_Wo[i] = make_float4(cvtf(v.x), cvtf(v.y), cvtf(v.z), cvtf(v.w));
}

// ============================================================================
// Kernel 0b: transpose + tf32-round QKV weights once: g_Wt[h][w][e][d].
// grid 48 (= 16h x 3w), 256 threads.
// ============================================================================
__global__ void prep_w(const float* __restrict__ Wq, const float* __restrict__ Wk,
                       const float* __restrict__ Wv) {
    const float* Wsrc[3] = { Wq, Wk, Wv };
    const int hw = blockIdx.x, h = hw / 3, w = hw % 3;
    const float* src = Wsrc[w] + (size_t)h * HD * HD;
    float* dst = g_Wt + (size_t)hw * HD * HD;
    for (int i = threadIdx.x; i < HD * HD; i += 256) {
        int d = i & 63, e = i >> 6;
        dst[e * 64 + d] = cvtf(src[d * 64 + e]);   // coalesced writes
    }
}

// ============================================================================
// Kernel 0c: per-batch key compaction (sorted unmasked indices + count).
// ============================================================================
__global__ void build_idx(const int* __restrict__ mask) {
    __shared__ int wsum[33];
    const int b = blockIdx.x, tid = threadIdx.x;
    const int lane = tid & 31, w = tid >> 5;
    const int flag = mask[b * SS + tid] ? 0 : 1;   // 1 = unmasked (keep)
    unsigned bal = __ballot_sync(0xffffffffu, flag);
    int pre = __popc(bal & ((1u << lane) - 1u));
    if (lane == 0) wsum[w] = __popc(bal);
    __syncthreads();
    if (tid == 0) {
        int s = 0;
        for (int i = 0; i < 32; ++i) { int tt = wsum[i]; wsum[i] = s; s += tt; }
        wsum[32] = s;
        g_nb[b] = s;
    }
    __syncthreads();
    const int nb = wsum[32];
    if (tid >= nb) g_idx[b * SS + tid] = 0;
    if (flag) g_idx[b * SS + wsum[w] + pre] = tid;
}

// ============================================================================
// Kernel 1: fused QKV projection. grid (8, 16, 8), 512 threads (16 warps).
// Wt staged via cp.async (pre-transposed+rounded); x staged LDG->cvt->STS.
// ============================================================================
#define PP 68
#define PRJ_WS   (128 * PP)
#define PRJ_BIAS (128 * PP + 192 * PP)
#define PRJ_SMEM_F (PRJ_BIAS + 192)

__global__ __launch_bounds__(512) void proj_mma(
    const float* __restrict__ x,
    const float* __restrict__ bq, const float* __restrict__ bk,
    const float* __restrict__ bv)
{
    extern __shared__ float sm[];
    float* xs = sm;
    float* ws = sm + PRJ_WS;
    float* sbias = sm + PRJ_BIAS;
    const uint32_t sb = smem_u32(sm);

    const int b = blockIdx.z, h = blockIdx.y, s0 = blockIdx.x * 128;
    const int tid = threadIdx.x, wid = tid >> 5, lane = tid & 31;
    const int g = lane >> 2, t = lane & 3;
    const int wr = wid & 3, wc = wid >> 2;
    const int r0 = wr * 32, c0 = wc * 48;

    // async Wt tiles (192 rows x 64 floats, already transposed+rounded)
    for (int i = tid; i < 192 * 16; i += 512) {
        int r = i >> 4, c4 = (i & 15) << 2;
        cpa16(sb + (uint32_t)(PRJ_WS + r * PP + c4) * 4,
              &g_Wt[((size_t)h * 192 + r) * 64 + c4]);
    }
    CP_COMMIT();

    // x: single LDG -> cvt -> STS pass (overlaps with Wt flight)
    for (int i = tid; i < 128 * 16; i += 512) {
        int r = i >> 4, c4 = (i & 15) << 2;
        float4 v = *(const float4*)&x[((size_t)(b * SS + s0 + r)) * DD + h * HD + c4];
        *(float4*)&xs[r * PP + c4] = make_float4(cvtf(v.x), cvtf(v.y), cvtf(v.z), cvtf(v.w));
    }
    if (tid < 192) {
        int w = tid >> 6, e = tid & 63;
        const float* bsrc[3] = { bq, bk, bv };
        sbias[tid] = bsrc[w][h * HD + e];
    }
    CP_WAIT(0);
    __syncthreads();

    float acc[2][6][4] = {};
    #pragma unroll
    for (int kk = 0; kk < 8; ++kk) {
        uint32_t a0[4], a1[4];
        lda(a0, xs, PP, r0, kk * 8, g, t);
        lda(a1, xs, PP, r0 + 16, kk * 8, g, t);
        #pragma unroll
        for (int n = 0; n < 6; ++n) {
            uint32_t bb[2];
            ldb_nk(bb, ws, PP, c0 + n * 8, kk * 8, g, t);
            mma8(acc[0][n], a0, bb);
            mma8(acc[1][n], a1, bb);
        }
    }

    float* gdst[3] = { g_Q, g_K, g_V };
    #pragma unroll
    for (int m = 0; m < 2; ++m) {
        #pragma unroll
        for (int n = 0; n < 6; ++n) {
            int gcol = c0 + n * 8 + t * 2;
            int w = gcol >> 6, lcol = gcol & 63;
            float b0 = sbias[gcol], b1 = sbias[gcol + 1];
            int row = s0 + r0 + m * 16 + g;
            float* outp = gdst[w];
            size_t base0 = ((size_t)((b * HH + h) * SS + row)) * HD + lcol;
            size_t base1 = ((size_t)((b * HH + h) * SS + row + 8)) * HD + lcol;
            *(float2*)&outp[base0] = make_float2(cvtf(acc[m][n][0] + b0), cvtf(acc[m][n][1] + b1));
            *(float2*)&outp[base1] = make_float2(cvtf(acc[m][n][2] + b0), cvtf(acc[m][n][3] + b1));
        }
    }
}

// ============================================================================
// Kernel 2: flash attention over COMPACTED keys (R12-identical).
// grid (8, 16, 8), 128 threads, ~106.5KB smem -> 2 CTAs/SM.
// ============================================================================
#define PA  68
#define AO_K 0
#define AO_V (128 * PA)
#define AO_Q (2 * 128 * PA)
#define AO_IDX (3 * 128 * PA)
#define ATTN_F (AO_IDX + 512)
#define EXPC 0.18033688f   // 0.125 * log2(e)

static __device__ __forceinline__ void s_half(float p[2][8][4], const float* Qs,
                                              const float* Ks, int r0, int n0,
                                              int g, int t) {
    #pragma unroll
    for (int m = 0; m < 2; ++m)
        #pragma unroll
        for (int n = 0; n < 8; ++n)
            #pragma unroll
            for (int j = 0; j < 4; ++j) p[m][n][j] = 0.f;
    #pragma unroll
    for (int kk = 0; kk < 8; ++kk) {
        uint32_t a0[4], a1[4];
        lda(a0, Qs, PA, r0, kk * 8, g, t);
        lda(a1, Qs, PA, r0 + 16, kk * 8, g, t);
        #pragma unroll
        for (int n = 0; n < 8; ++n) {
            uint32_t bb[2];
            ldb_nk(bb, Ks, PA, n0 + n * 8, kk * 8, g, t);
            mma8(p[0][n], a0, bb);
            mma8(p[1][n], a1, bb);
        }
    }
}

static __device__ __forceinline__ void exp_half(float p[2][8][4], int colbase, int nb,
                                                float rs[2][2], int t) {
    #pragma unroll
    for (int m = 0; m < 2; ++m)
        #pragma unroll
        for (int n = 0; n < 8; ++n) {
            int col = colbase + n * 8 + t * 2;
            float mx = (col < nb) ? 1.f : 0.f;
            float my = (col + 1 < nb) ? 1.f : 0.f;
            p[m][n][0] = ex2f(p[m][n][0] * EXPC) * mx;
            p[m][n][1] = ex2f(p[m][n][1] * EXPC) * my;
            p[m][n][2] = ex2f(p[m][n][2] * EXPC) * mx;
            p[m][n][3] = ex2f(p[m][n][3] * EXPC) * my;
            rs[m][0] += p[m][n][0] + p[m][n][1];
            rs[m][1] += p[m][n][2] + p[m][n][3];
        }
}

static __device__ __forceinline__ void pv_half(float o[2][8][4], const float p[2][8][4],
                                               const float* Vs, int n0, int g, int t) {
    #pragma unroll
    for (int kkp = 0; kkp < 8; ++kkp) {
        uint32_t A0[4] = { __float_as_uint(p[0][kkp][0]), __float_as_uint(p[0][kkp][2]),
                           __float_as_uint(p[0][kkp][1]), __float_as_uint(p[0][kkp][3]) };
        uint32_t A1[4] = { __float_as_uint(p[1][kkp][0]), __float_as_uint(p[1][kkp][2]),
                           __float_as_uint(p[1][kkp][1]), __float_as_uint(p[1][kkp][3]) };
        const float* vrow0 = Vs + (n0 + kkp * 8 + 2 * t) * PA;
        const float* vrow1 = vrow0 + PA;
        #pragma unroll
        for (int n = 0; n < 8; ++n) {
            uint32_t bb[2];
            bb[0] = __float_as_uint(vrow0[n * 8 + g]);
            bb[1] = __float_as_uint(vrow1[n * 8 + g]);
            mma8(o[0][n], A0, bb);
            mma8(o[1][n], A1, bb);
        }
    }
}

__global__ __launch_bounds__(128, 2) void attn_mma()
{
    extern __shared__ float sm[];
    float* Ks = sm + AO_K;
    float* Vs = sm + AO_V;
    float* Qs = sm + AO_Q;
    unsigned short* s_idx = (unsigned short*)(sm + AO_IDX);
    const uint32_t sb = smem_u32(sm);

    const int b = blockIdx.z, h = blockIdx.y, q0 = blockIdx.x * 128;
    const int tid = threadIdx.x, wid = tid >> 5, lane = tid & 31;
    const int g = lane >> 2, t = lane & 3;
    const int r0 = wid * 32;

    const size_t bh = (size_t)(b * HH + h) * SS * HD;
    const float* Qp = g_Q + bh;
    const float* Kp = g_K + bh;
    const float* Vp = g_V + bh;

    for (int i = tid; i < SS; i += 128)
        s_idx[i] = (unsigned short)g_idx[b * SS + i];
    const int nb = g_nb[b];
    const int ntiles = (nb + 127) >> 7;
    __syncthreads();

    for (int i = tid; i < 128 * 16; i += 128) {
        int r = i >> 4, c4 = (i & 15) << 2;
        int src = s_idx[r];
        cpa16(sb + (uint32_t)(AO_K + r * PA + c4) * 4, &Kp[(size_t)src * HD + c4]);
    }
    CP_COMMIT();
    for (int i = tid; i < 128 * 16; i += 128) {
        int r = i >> 4, c4 = (i & 15) << 2;
        int src = s_idx[r];
        cpa16(sb + (uint32_t)(AO_V + r * PA + c4) * 4, &Vp[(size_t)src * HD + c4]);
        cpa16(sb + (uint32_t)(AO_Q + r * PA + c4) * 4, &Qp[(size_t)(q0 + r) * HD + c4]);
    }
    CP_COMMIT();
    CP_WAIT(0);
    __syncthreads();

    float o[2][8][4] = {};
    float rs[2][2] = {};
    float p[2][8][4];

    for (int kt = 0; kt < ntiles; ++kt) {
        CP_WAIT(1);
        __syncthreads();

        s_half(p, Qs, Ks, r0, 0, g, t);
        exp_half(p, kt * 128, nb, rs, t);
        CP_WAIT(0);
        __syncthreads();
        pv_half(o, p, Vs, 0, g, t);

        s_half(p, Qs, Ks, r0, 64, g, t);
        exp_half(p, kt * 128 + 64, nb, rs, t);
        __syncthreads();
        if (kt + 1 < ntiles) {
            for (int i = tid; i < 128 * 16; i += 128) {
                int r = i >> 4, c4 = (i & 15) << 2;
                int src = s_idx[(kt + 1) * 128 + r];
                cpa16(sb + (uint32_t)(AO_K + r * PA + c4) * 4,
                      &Kp[(size_t)src * HD + c4]);
            }
        }
        CP_COMMIT();
        pv_half(o, p, Vs, 64, g, t);
        __syncthreads();
        if (kt + 1 < ntiles) {
            for (int i = tid; i < 128 * 16; i += 128) {
                int r = i >> 4, c4 = (i & 15) << 2;
                int src = s_idx[(kt + 1) * 128 + r];
                cpa16(sb + (uint32_t)(AO_V + r * PA + c4) * 4,
                      &Vp[(size_t)src * HD + c4]);
            }
        }
        CP_COMMIT();
    }

    #pragma unroll
    for (int m = 0; m < 2; ++m)
        #pragma unroll
        for (int j = 0; j < 2; ++j) {
            rs[m][j] += __shfl_xor_sync(0xffffffffu, rs[m][j], 1);
            rs[m][j] += __shfl_xor_sync(0xffffffffu, rs[m][j], 2);
        }

    #pragma unroll
    for (int m = 0; m < 2; ++m) {
        const float inv0 = 1.0f / rs[m][0], inv1 = 1.0f / rs[m][1];
        const int row = q0 + r0 + m * 16 + g;
        #pragma unroll
        for (int n = 0; n < 8; ++n) {
            int col = n * 8 + t * 2;
            size_t base0 = ((size_t)(b * SS + row)) * DD + h * HD + col;
            size_t base1 = ((size_t)(b * SS + row + 8)) * DD + h * HD + col;
            *(float2*)&g_C[base0] = make_float2(cvtf(o[m][n][0] * inv0), cvtf(o[m][n][1] * inv0));
            *(float2*)&g_C[base1] = make_float2(cvtf(o[m][n][2] * inv1), cvtf(o[m][n][3] * inv1));
        }
    }
}

// ============================================================================
// Kernel 3: out-proj Y = C @ Wo^T + bo. grid (8, 64), 128 threads (4 warps).
// Block 128x128, warp 64x64 (1.0 LDS/mma). THREE-buffer cp.async ring with
// ONE barrier per chunk (issue-before-compute into the buffer freed at the
// previous chunk). 110.6KB smem -> 2 CTAs/SM.
// ============================================================================
#define PO 36
#define OB_STRIDE (2 * 128 * PO)

__global__ __launch_bounds__(128, 2) void outproj_mma(
    const float* __restrict__ bo, float* __restrict__ y)
{
    extern __shared__ float sm[];
    const uint32_t sb = smem_u32(sm);

    const int n0 = blockIdx.x * 128;
    const int m0 = blockIdx.y * 128;
    const int tid = threadIdx.x, wid = tid >> 5, lane = tid & 31;
    const int g = lane >> 2, t = lane & 3;
    const int wr = wid & 1, wc = wid >> 1;
    const int r0 = wr * 64, c0 = wc * 64;

    auto issue = [&](int ch, int buf) {
        const uint32_t bofs = (uint32_t)(buf * OB_STRIDE);
        for (int i = tid; i < 128 * 8; i += 128) {
            int r = i >> 3, c4 = (i & 7) << 2;
            cpa16(sb + (bofs + (uint32_t)(r * PO + c4)) * 4,
                  &g_C[(size_t)(m0 + r) * DD + ch * 32 + c4]);
            cpa16(sb + (bofs + (uint32_t)(128 * PO + r * PO + c4)) * 4,
                  &g_Wo[(size_t)(n0 + r) * DD + ch * 32 + c4]);
        }
        CP_COMMIT();
    };
    issue(0, 0);
    issue(1, 1);

    float acc[4][8][4] = {};
    int cbuf = 0, ibuf = 2;
    for (int ch = 0; ch < 32; ++ch) {
        CP_WAIT(1);
        __syncthreads();     // single barrier per chunk
        // prefetch ch+2 into the buffer freed when chunk ch-1 completed
        if (ch + 2 < 32) issue(ch + 2, ibuf);
        else CP_COMMIT();    // keep group accounting uniform

        const float* Cs = sm + cbuf * OB_STRIDE;
        const float* Ws = Cs + 128 * PO;
        #pragma unroll
        for (int kk = 0; kk < 4; ++kk) {
            uint32_t a_[4][4];
            #pragma unroll
            for (int m = 0; m < 4; ++m)
                lda(a_[m], Cs, PO, r0 + m * 16, kk * 8, g, t);
            #pragma unroll
            for (int n = 0; n < 8; ++n) {
                uint32_t bb[2];
                ldb_nk(bb, Ws, PO, c0 + n * 8, kk * 8, g, t);
                #pragma unroll
                for (int m = 0; m < 4; ++m)
                    mma8(acc[m][n], a_[m], bb);
            }
        }
        cbuf = (cbuf == 2) ? 0 : cbuf + 1;
        ibuf = (ibuf == 2) ? 0 : ibuf + 1;
    }

    #pragma unroll
    for (int m = 0; m < 4; ++m) {
        #pragma unroll
        for (int n = 0; n < 8; ++n) {
            int col = c0 + n * 8 + t * 2;
            float b0 = bo[n0 + col], b1 = bo[n0 + col + 1];
            int row = m0 + r0 + m * 16 + g;
            size_t base0 = (size_t)row * DD + n0 + col;
            size_t base1 = (size_t)(row + 8) * DD + n0 + col;
            *(float2*)&y[base0] = make_float2(acc[m][n][0] + b0, acc[m][n][1] + b1);
            *(float2*)&y[base1] = make_float2(acc[m][n][2] + b0, acc[m][n][3] + b1);
        }
    }
}

// ============================================================================
extern "C" void kernel_launch(void* const* d_in, const int* in_sizes, int n_in,
                              void* d_out, int out_size)
{
    const float* x  = (const float*)d_in[0];
    const int* mk   = (const int*)d_in[1];
    const float* Wq = (const float*)d_in[2];
    const float* bq = (const float*)d_in[3];
    const float* Wk = (const float*)d_in[4];
    const float* bk = (const float*)d_in[5];
    const float* Wv = (const float*)d_in[6];
    const float* bv = (const float*)d_in[7];
    const float* Wo = (const float*)d_in[8];
    const float* bo = (const float*)d_in[9];
    float* y = (float*)d_out;

    const int smem_proj = PRJ_SMEM_F * 4;     // ~88 KB
    const int smem_attn = ATTN_F * 4;         // ~106.5 KB -> 2 CTAs/SM
    const int smem_out  = 3 * OB_STRIDE * 4;  // ~110.6 KB -> 2 CTAs/SM
    cudaFuncSetAttribute(proj_mma, cudaFuncAttributeMaxDynamicSharedMemorySize, smem_proj);
    cudaFuncSetAttribute(attn_mma, cudaFuncAttributeMaxDynamicSharedMemorySize, smem_attn);
    cudaFuncSetAttribute(outproj_mma, cudaFuncAttributeMaxDynamicSharedMemorySize, smem_out);

    round_wo<<<DD * DD / 1024, 256>>>(Wo);
    prep_w<<<HH * 3, 256>>>(Wq, Wk, Wv);
    build_idx<<<BB, SS>>>(mk);
    proj_mma<<<dim3(SS / 128, HH, BB), 512, smem_proj>>>(x, bq, bk, bv);
    attn_mma<<<dim3(SS / 128, HH, BB), 128, smem_attn>>>();
    outproj_mma<<<dim3(DD / 128, BB * SS / 128), 128, smem_out>>>(bo, y);
}

// round 14
// speedup vs baseline: 1.0682x; 1.0682x over previous
#include <cuda_runtime.h>
#include <cstdint>

#define BB 8
#define SS 1024
#define DD 1024
#define HH 16
#define HD 64

// Scratch (device globals). All contents tf32-rounded fp32 (rounded once, rna).
__device__ float g_Q[BB*HH*SS*HD];
__device__ float g_K[BB*HH*SS*HD];
__device__ float g_V[BB*HH*SS*HD];
__device__ float g_C[(size_t)BB*SS*DD];
__device__ float g_Wo[DD*DD];
__device__ int   g_idx[BB*SS];   // per-batch compacted unmasked key indices
__device__ int   g_nb[BB];       // per-batch unmasked count

// ---------------- helpers ----------------
static __device__ __forceinline__ uint32_t cvt_tf32(float f) {
    uint32_t u; asm("cvt.rna.tf32.f32 %0, %1;" : "=r"(u) : "f"(f)); return u;
}
static __device__ __forceinline__ float cvtf(float f) { return __uint_as_float(cvt_tf32(f)); }
static __device__ __forceinline__ float ex2f(float x) {
    float y; asm("ex2.approx.f32 %0, %1;" : "=f"(y) : "f"(x)); return y;
}
static __device__ __forceinline__ void mma8(float* d, const uint32_t* a, const uint32_t* b) {
    asm volatile("mma.sync.aligned.m16n8k8.row.col.f32.tf32.tf32.f32 "
        "{%0,%1,%2,%3}, {%4,%5,%6,%7}, {%8,%9}, {%0,%1,%2,%3};"
        : "+f"(d[0]), "+f"(d[1]), "+f"(d[2]), "+f"(d[3])
        : "r"(a[0]), "r"(a[1]), "r"(a[2]), "r"(a[3]), "r"(b[0]), "r"(b[1]));
}
static __device__ __forceinline__ void lda(uint32_t* a, const float* s, int P,
                                           int r0, int k0, int g, int t) {
    a[0] = __float_as_uint(s[(r0 + g) * P + k0 + t]);
    a[1] = __float_as_uint(s[(r0 + g + 8) * P + k0 + t]);
    a[2] = __float_as_uint(s[(r0 + g) * P + k0 + t + 4]);
    a[3] = __float_as_uint(s[(r0 + g + 8) * P + k0 + t + 4]);
}
static __device__ __forceinline__ void ldb_nk(uint32_t* b, const float* s, int P,
                                              int n0, int k0, int g, int t) {
    b[0] = __float_as_uint(s[(n0 + g) * P + k0 + t]);
    b[1] = __float_as_uint(s[(n0 + g) * P + k0 + t + 4]);
}
static __device__ __forceinline__ uint32_t smem_u32(const void* p) {
    uint32_t a;
    asm("{ .reg .u64 t; cvta.to.shared.u64 t, %1; cvt.u32.u64 %0, t; }" : "=r"(a) : "l"(p));
    return a;
}
static __device__ __forceinline__ void cpa16(uint32_t dst, const void* src) {
    asm volatile("cp.async.ca.shared.global [%0], [%1], 16;" :: "r"(dst), "l"(src));
}
#define CP_COMMIT() asm volatile("cp.async.commit_group;" ::: "memory")
#define CP_WAIT(n)  asm volatile("cp.async.wait_group %0;" :: "n"(n) : "memory")

// ============================================================================
// Kernel 0a: tf32-round Wo (once).
// ============================================================================
__global__ void round_wo(const float* __restrict__ Wo) {
    int i = (blockIdx.x * 256 + threadIdx.x) * 4;
    float4 v = *(const float4*)&Wo[i];
    *(float4*)&g_Wo[i] = make_float4(cvtf(v.x), cvtf(v.y), cvtf(v.z), cvtf(v.w));
}

// ============================================================================
// Kernel 0b: per-batch key compaction (sorted unmasked indices + count).
// ============================================================================
__global__ void build_idx(const int* __restrict__ mask) {
    __shared__ int wsum[33];
    const int b = blockIdx.x, tid = threadIdx.x;
    const int lane = tid & 31, w = tid >> 5;
    const int flag = mask[b * SS + tid] ? 0 : 1;   // 1 = unmasked (keep)
    unsigned bal = __ballot_sync(0xffffffffu, flag);
    int pre = __popc(bal & ((1u << lane) - 1u));
    if (lane == 0) wsum[w] = __popc(bal);
    __syncthreads();
    if (tid == 0) {
        int s = 0;
        for (int i = 0; i < 32; ++i) { int tt = wsum[i]; wsum[i] = s; s += tt; }
        wsum[32] = s;
        g_nb[b] = s;
    }
    __syncthreads();
    const int nb = wsum[32];
    if (tid >= nb) g_idx[b * SS + tid] = 0;          // pad slots -> row 0 (zeroed later)
    if (flag) g_idx[b * SS + wsum[w] + pre] = tid;   // distinct slots (< nb)
}

// ============================================================================
// Kernel 1: fused QKV projection (R12-identical). grid (8, 16, 8), 512 threads.
// ============================================================================
#define PP 68
#define PRJ_WS   (128 * PP)
#define PRJ_BIAS (128 * PP + 192 * PP)
#define PRJ_SMEM_F (PRJ_BIAS + 192)

__global__ __launch_bounds__(512) void proj_mma(
    const float* __restrict__ x,
    const float* __restrict__ Wq, const float* __restrict__ bq,
    const float* __restrict__ Wk, const float* __restrict__ bk,
    const float* __restrict__ Wv, const float* __restrict__ bv)
{
    extern __shared__ float sm[];
    float* xs = sm;
    float* ws = sm + PRJ_WS;
    float* sbias = sm + PRJ_BIAS;
    const uint32_t sb = smem_u32(sm);

    const int b = blockIdx.z, h = blockIdx.y, s0 = blockIdx.x * 128;
    const int tid = threadIdx.x, wid = tid >> 5, lane = tid & 31;
    const int g = lane >> 2, t = lane & 3;
    const int wr = wid & 3, wc = wid >> 2;
    const int r0 = wr * 32, c0 = wc * 48;

    for (int i = tid; i < 128 * 16; i += 512) {
        int r = i >> 4, c4 = (i & 15) << 2;
        cpa16(sb + (uint32_t)(r * PP + c4) * 4,
              &x[((size_t)(b * SS + s0 + r)) * DD + h * HD + c4]);
    }
    CP_COMMIT();

    {
        const float* Wsrc[3] = { Wq + (size_t)h * HD * HD, Wk + (size_t)h * HD * HD,
                                 Wv + (size_t)h * HD * HD };
        for (int i = tid; i < 3 * 4096; i += 512) {
            int w = i >> 12, r = i & 4095, d = r >> 6, e = r & 63;
            ws[(w * 64 + e) * PP + d] = cvtf(Wsrc[w][r]);
        }
        if (tid < 192) {
            int w = tid >> 6, e = tid & 63;
            const float* bsrc[3] = { bq, bk, bv };
            sbias[tid] = bsrc[w][h * HD + e];
        }
    }
    CP_WAIT(0);
    __syncthreads();
    for (int i = tid; i < 128 * 16; i += 512) {
        int r = i >> 4, c4 = (i & 15) << 2;
        float4 v = *(float4*)&xs[r * PP + c4];
        *(float4*)&xs[r * PP + c4] = make_float4(cvtf(v.x), cvtf(v.y), cvtf(v.z), cvtf(v.w));
    }
    __syncthreads();

    float acc[2][6][4] = {};
    #pragma unroll
    for (int kk = 0; kk < 8; ++kk) {
        uint32_t a0[4], a1[4];
        lda(a0, xs, PP, r0, kk * 8, g, t);
        lda(a1, xs, PP, r0 + 16, kk * 8, g, t);
        #pragma unroll
        for (int n = 0; n < 6; ++n) {
            uint32_t bb[2];
            ldb_nk(bb, ws, PP, c0 + n * 8, kk * 8, g, t);
            mma8(acc[0][n], a0, bb);
            mma8(acc[1][n], a1, bb);
        }
    }

    float* gdst[3] = { g_Q, g_K, g_V };
    #pragma unroll
    for (int m = 0; m < 2; ++m) {
        #pragma unroll
        for (int n = 0; n < 6; ++n) {
            int gcol = c0 + n * 8 + t * 2;
            int w = gcol >> 6, lcol = gcol & 63;
            float b0 = sbias[gcol], b1 = sbias[gcol + 1];
            int row = s0 + r0 + m * 16 + g;
            float* outp = gdst[w];
            size_t base0 = ((size_t)((b * HH + h) * SS + row)) * HD + lcol;
            size_t base1 = ((size_t)((b * HH + h) * SS + row + 8)) * HD + lcol;
            *(float2*)&outp[base0] = make_float2(cvtf(acc[m][n][0] + b0), cvtf(acc[m][n][1] + b1));
            *(float2*)&outp[base1] = make_float2(cvtf(acc[m][n][2] + b0), cvtf(acc[m][n][3] + b1));
        }
    }
}

// ============================================================================
// Kernel 2: flash attention over COMPACTED keys (R12-identical).
// grid (8, 16, 8), 128 threads, ~106.5KB smem -> 2 CTAs/SM.
// ============================================================================
#define PA  68
#define AO_K 0
#define AO_V (128 * PA)
#define AO_Q (2 * 128 * PA)
#define AO_IDX (3 * 128 * PA)
#define ATTN_F (AO_IDX + 512)
#define EXPC 0.18033688f   // 0.125 * log2(e)

static __device__ __forceinline__ void s_half(float p[2][8][4], const float* Qs,
                                              const float* Ks, int r0, int n0,
                                              int g, int t) {
    #pragma unroll
    for (int m = 0; m < 2; ++m)
        #pragma unroll
        for (int n = 0; n < 8; ++n)
            #pragma unroll
            for (int j = 0; j < 4; ++j) p[m][n][j] = 0.f;
    #pragma unroll
    for (int kk = 0; kk < 8; ++kk) {
        uint32_t a0[4], a1[4];
        lda(a0, Qs, PA, r0, kk * 8, g, t);
        lda(a1, Qs, PA, r0 + 16, kk * 8, g, t);
        #pragma unroll
        for (int n = 0; n < 8; ++n) {
            uint32_t bb[2];
            ldb_nk(bb, Ks, PA, n0 + n * 8, kk * 8, g, t);
            mma8(p[0][n], a0, bb);
            mma8(p[1][n], a1, bb);
        }
    }
}

static __device__ __forceinline__ void exp_half(float p[2][8][4], int colbase, int nb,
                                                float rs[2][2], int t) {
    #pragma unroll
    for (int m = 0; m < 2; ++m)
        #pragma unroll
        for (int n = 0; n < 8; ++n) {
            int col = colbase + n * 8 + t * 2;
            float mx = (col < nb) ? 1.f : 0.f;
            float my = (col + 1 < nb) ? 1.f : 0.f;
            p[m][n][0] = ex2f(p[m][n][0] * EXPC) * mx;
            p[m][n][1] = ex2f(p[m][n][1] * EXPC) * my;
            p[m][n][2] = ex2f(p[m][n][2] * EXPC) * mx;
            p[m][n][3] = ex2f(p[m][n][3] * EXPC) * my;
            rs[m][0] += p[m][n][0] + p[m][n][1];
            rs[m][1] += p[m][n][2] + p[m][n][3];
        }
}

static __device__ __forceinline__ void pv_half(float o[2][8][4], const float p[2][8][4],
                                               const float* Vs, int n0, int g, int t) {
    #pragma unroll
    for (int kkp = 0; kkp < 8; ++kkp) {
        uint32_t A0[4] = { __float_as_uint(p[0][kkp][0]), __float_as_uint(p[0][kkp][2]),
                           __float_as_uint(p[0][kkp][1]), __float_as_uint(p[0][kkp][3]) };
        uint32_t A1[4] = { __float_as_uint(p[1][kkp][0]), __float_as_uint(p[1][kkp][2]),
                           __float_as_uint(p[1][kkp][1]), __float_as_uint(p[1][kkp][3]) };
        const float* vrow0 = Vs + (n0 + kkp * 8 + 2 * t) * PA;
        const float* vrow1 = vrow0 + PA;
        #pragma unroll
        for (int n = 0; n < 8; ++n) {
            uint32_t bb[2];
            bb[0] = __float_as_uint(vrow0[n * 8 + g]);
            bb[1] = __float_as_uint(vrow1[n * 8 + g]);
            mma8(o[0][n], A0, bb);
            mma8(o[1][n], A1, bb);
        }
    }
}

__global__ __launch_bounds__(128, 2) void attn_mma()
{
    extern __shared__ float sm[];
    float* Ks = sm + AO_K;
    float* Vs = sm + AO_V;
    float* Qs = sm + AO_Q;
    unsigned short* s_idx = (unsigned short*)(sm + AO_IDX);
    const uint32_t sb = smem_u32(sm);

    const int b = blockIdx.z, h = blockIdx.y, q0 = blockIdx.x * 128;
    const int tid = threadIdx.x, wid = tid >> 5, lane = tid & 31;
    const int g = lane >> 2, t = lane & 3;
    const int r0 = wid * 32;

    const size_t bh = (size_t)(b * HH + h) * SS * HD;
    const float* Qp = g_Q + bh;
    const float* Kp = g_K + bh;
    const float* Vp = g_V + bh;

    for (int i = tid; i < SS; i += 128)
        s_idx[i] = (unsigned short)g_idx[b * SS + i];
    const int nb = g_nb[b];
    const int ntiles = (nb + 127) >> 7;
    __syncthreads();

    for (int i = tid; i < 128 * 16; i += 128) {
        int r = i >> 4, c4 = (i & 15) << 2;
        int src = s_idx[r];
        cpa16(sb + (uint32_t)(AO_K + r * PA + c4) * 4, &Kp[(size_t)src * HD + c4]);
    }
    CP_COMMIT();
    for (int i = tid; i < 128 * 16; i += 128) {
        int r = i >> 4, c4 = (i & 15) << 2;
        int src = s_idx[r];
        cpa16(sb + (uint32_t)(AO_V + r * PA + c4) * 4, &Vp[(size_t)src * HD + c4]);
        cpa16(sb + (uint32_t)(AO_Q + r * PA + c4) * 4, &Qp[(size_t)(q0 + r) * HD + c4]);
    }
    CP_COMMIT();
    CP_WAIT(0);
    __syncthreads();

    float o[2][8][4] = {};
    float rs[2][2] = {};
    float p[2][8][4];

    for (int kt = 0; kt < ntiles; ++kt) {
        CP_WAIT(1);
        __syncthreads();

        s_half(p, Qs, Ks, r0, 0, g, t);
        exp_half(p, kt * 128, nb, rs, t);
        CP_WAIT(0);
        __syncthreads();
        pv_half(o, p, Vs, 0, g, t);

        s_half(p, Qs, Ks, r0, 64, g, t);
        exp_half(p, kt * 128 + 64, nb, rs, t);
        __syncthreads();
        if (kt + 1 < ntiles) {
            for (int i = tid; i < 128 * 16; i += 128) {
                int r = i >> 4, c4 = (i & 15) << 2;
                int src = s_idx[(kt + 1) * 128 + r];
                cpa16(sb + (uint32_t)(AO_K + r * PA + c4) * 4,
                      &Kp[(size_t)src * HD + c4]);
            }
        }
        CP_COMMIT();
        pv_half(o, p, Vs, 64, g, t);
        __syncthreads();
        if (kt + 1 < ntiles) {
            for (int i = tid; i < 128 * 16; i += 128) {
                int r = i >> 4, c4 = (i & 15) << 2;
                int src = s_idx[(kt + 1) * 128 + r];
                cpa16(sb + (uint32_t)(AO_V + r * PA + c4) * 4,
                      &Vp[(size_t)src * HD + c4]);
            }
        }
        CP_COMMIT();
    }

    #pragma unroll
    for (int m = 0; m < 2; ++m)
        #pragma unroll
        for (int j = 0; j < 2; ++j) {
            rs[m][j] += __shfl_xor_sync(0xffffffffu, rs[m][j], 1);
            rs[m][j] += __shfl_xor_sync(0xffffffffu, rs[m][j], 2);
        }

    #pragma unroll
    for (int m = 0; m < 2; ++m) {
        const float inv0 = 1.0f / rs[m][0], inv1 = 1.0f / rs[m][1];
        const int row = q0 + r0 + m * 16 + g;
        #pragma unroll
        for (int n = 0; n < 8; ++n) {
            int col = n * 8 + t * 2;
            size_t base0 = ((size_t)(b * SS + row)) * DD + h * HD + col;
            size_t base1 = ((size_t)(b * SS + row + 8)) * DD + h * HD + col;
            *(float2*)&g_C[base0] = make_float2(cvtf(o[m][n][0] * inv0), cvtf(o[m][n][1] * inv0));
            *(float2*)&g_C[base1] = make_float2(cvtf(o[m][n][2] * inv1), cvtf(o[m][n][3] * inv1));
        }
    }
}

// ============================================================================
// Kernel 3: out-proj Y = C @ Wo^T + bo. grid (8, 64), 128 threads (4 warps).
// Block 128x128, warp 64x64 (1.0 LDS/mma), double-buffered k-chunks of 32.
// 72KB smem + launch_bounds(128,3) regs cap -> 3 CTAs/SM (12 warps,
// grid 512 over 444 slots = 1.15 waves instead of 1.73).
// ============================================================================
#define PO 36
#define OB_STRIDE (2 * 128 * PO)

__global__ __launch_bounds__(128, 3) void outproj_mma(
    const float* __restrict__ bo, float* __restrict__ y)
{
    extern __shared__ float sm[];
    const uint32_t sb = smem_u32(sm);

    const int n0 = blockIdx.x * 128;
    const int m0 = blockIdx.y * 128;
    const int tid = threadIdx.x, wid = tid >> 5, lane = tid & 31;
    const int g = lane >> 2, t = lane & 3;
    const int wr = wid & 1, wc = wid >> 1;
    const int r0 = wr * 64, c0 = wc * 64;

    auto issue = [&](int ch, int buf) {
        const uint32_t bofs = (uint32_t)(buf * OB_STRIDE);
        for (int i = tid; i < 128 * 8; i += 128) {
            int r = i >> 3, c4 = (i & 7) << 2;
            cpa16(sb + (bofs + (uint32_t)(r * PO + c4)) * 4,
                  &g_C[(size_t)(m0 + r) * DD + ch * 32 + c4]);
            cpa16(sb + (bofs + (uint32_t)(128 * PO + r * PO + c4)) * 4,
                  &g_Wo[(size_t)(n0 + r) * DD + ch * 32 + c4]);
        }
        CP_COMMIT();
    };
    issue(0, 0);
    issue(1, 1);

    float acc[4][8][4] = {};
    for (int ch = 0; ch < 32; ++ch) {
        CP_WAIT(1);
        __syncthreads();
        const float* Cs = sm + (ch & 1) * OB_STRIDE;
        const float* Ws = Cs + 128 * PO;
        #pragma unroll
        for (int kk = 0; kk < 4; ++kk) {
            uint32_t a_[4][4];
            #pragma unroll
            for (int m = 0; m < 4; ++m)
                lda(a_[m], Cs, PO, r0 + m * 16, kk * 8, g, t);
            #pragma unroll
            for (int n = 0; n < 8; ++n) {
                uint32_t bb[2];
                ldb_nk(bb, Ws, PO, c0 + n * 8, kk * 8, g, t);
                #pragma unroll
                for (int m = 0; m < 4; ++m)
                    mma8(acc[m][n], a_[m], bb);
            }
        }
        __syncthreads();
        if (ch + 2 < 32) issue(ch + 2, ch & 1);
        else CP_COMMIT();
    }

    #pragma unroll
    for (int m = 0; m < 4; ++m) {
        #pragma unroll
        for (int n = 0; n < 8; ++n) {
            int col = c0 + n * 8 + t * 2;
            float b0 = bo[n0 + col], b1 = bo[n0 + col + 1];
            int row = m0 + r0 + m * 16 + g;
            size_t base0 = (size_t)row * DD + n0 + col;
            size_t base1 = (size_t)(row + 8) * DD + n0 + col;
            *(float2*)&y[base0] = make_float2(acc[m][n][0] + b0, acc[m][n][1] + b1);
            *(float2*)&y[base1] = make_float2(acc[m][n][2] + b0, acc[m][n][3] + b1);
        }
    }
}

// ============================================================================
extern "C" void kernel_launch(void* const* d_in, const int* in_sizes, int n_in,
                              void* d_out, int out_size)
{
    const float* x  = (const float*)d_in[0];
    const int* mk   = (const int*)d_in[1];
    const float* Wq = (const float*)d_in[2];
    const float* bq = (const float*)d_in[3];
    const float* Wk = (const float*)d_in[4];
    const float* bk = (const float*)d_in[5];
    const float* Wv = (const float*)d_in[6];
    const float* bv = (const float*)d_in[7];
    const float* Wo = (const float*)d_in[8];
    const float* bo = (const float*)d_in[9];
    float* y = (float*)d_out;

    const int smem_proj = PRJ_SMEM_F * 4;     // ~88 KB
    const int smem_attn = ATTN_F * 4;         // ~106.5 KB -> 2 CTAs/SM
    const int smem_out  = 2 * OB_STRIDE * 4;  // 72 KB -> 3 CTAs/SM
    cudaFuncSetAttribute(proj_mma, cudaFuncAttributeMaxDynamicSharedMemorySize, smem_proj);
    cudaFuncSetAttribute(attn_mma, cudaFuncAttributeMaxDynamicSharedMemorySize, smem_attn);
    cudaFuncSetAttribute(outproj_mma, cudaFuncAttributeMaxDynamicSharedMemorySize, smem_out);

    round_wo<<<DD * DD / 1024, 256>>>(Wo);
    build_idx<<<BB, SS>>>(mk);
    proj_mma<<<dim3(SS / 128, HH, BB), 512, smem_proj>>>(x, Wq, bq, Wk, bk, Wv, bv);
    attn_mma<<<dim3(SS / 128, HH, BB), 128, smem_attn>>>();
    outproj_mma<<<dim3(DD / 128, BB * SS / 128), 128, smem_out>>>(bo, y);
}

// round 15
// speedup vs baseline: 1.0909x; 1.0213x over previous
#include <cuda_runtime.h>
#include <cstdint>

#define BB 8
#define SS 1024
#define DD 1024
#define HH 16
#define HD 64

// Scratch (device globals). All contents tf32-rounded fp32 (rounded once, rna).
__device__ float g_Q[BB*HH*SS*HD];
__device__ float g_K[BB*HH*SS*HD];
__device__ float g_V[BB*HH*SS*HD];
__device__ float g_C[(size_t)BB*SS*DD];
__device__ float g_Wo[DD*DD];
__device__ int   g_idx[BB*SS];   // per-batch compacted unmasked key indices
__device__ int   g_nb[BB];       // per-batch unmasked count

// ---------------- helpers ----------------
static __device__ __forceinline__ uint32_t cvt_tf32(float f) {
    uint32_t u; asm("cvt.rna.tf32.f32 %0, %1;" : "=r"(u) : "f"(f)); return u;
}
static __device__ __forceinline__ float cvtf(float f) { return __uint_as_float(cvt_tf32(f)); }
static __device__ __forceinline__ float ex2f(float x) {
    float y; asm("ex2.approx.f32 %0, %1;" : "=f"(y) : "f"(x)); return y;
}
static __device__ __forceinline__ void mma8(float* d, const uint32_t* a, const uint32_t* b) {
    asm volatile("mma.sync.aligned.m16n8k8.row.col.f32.tf32.tf32.f32 "
        "{%0,%1,%2,%3}, {%4,%5,%6,%7}, {%8,%9}, {%0,%1,%2,%3};"
        : "+f"(d[0]), "+f"(d[1]), "+f"(d[2]), "+f"(d[3])
        : "r"(a[0]), "r"(a[1]), "r"(a[2]), "r"(a[3]), "r"(b[0]), "r"(b[1]));
}
static __device__ __forceinline__ void lda(uint32_t* a, const float* s, int P,
                                           int r0, int k0, int g, int t) {
    a[0] = __float_as_uint(s[(r0 + g) * P + k0 + t]);
    a[1] = __float_as_uint(s[(r0 + g + 8) * P + k0 + t]);
    a[2] = __float_as_uint(s[(r0 + g) * P + k0 + t + 4]);
    a[3] = __float_as_uint(s[(r0 + g + 8) * P + k0 + t + 4]);
}
static __device__ __forceinline__ void ldb_nk(uint32_t* b, const float* s, int P,
                                              int n0, int k0, int g, int t) {
    b[0] = __float_as_uint(s[(n0 + g) * P + k0 + t]);
    b[1] = __float_as_uint(s[(n0 + g) * P + k0 + t + 4]);
}
static __device__ __forceinline__ uint32_t smem_u32(const void* p) {
    uint32_t a;
    asm("{ .reg .u64 t; cvta.to.shared.u64 t, %1; cvt.u32.u64 %0, t; }" : "=r"(a) : "l"(p));
    return a;
}
static __device__ __forceinline__ void cpa16(uint32_t dst, const void* src) {
    asm volatile("cp.async.ca.shared.global [%0], [%1], 16;" :: "r"(dst), "l"(src));
}
#define CP_COMMIT() asm volatile("cp.async.commit_group;" ::: "memory")
#define CP_WAIT(n)  asm volatile("cp.async.wait_group %0;" :: "n"(n) : "memory")

// ============================================================================
// Kernel 0a: tf32-round Wo (once).
// ============================================================================
__global__ void round_wo(const float* __restrict__ Wo) {
    int i = (blockIdx.x * 256 + threadIdx.x) * 4;
    float4 v = *(const float4*)&Wo[i];
    *(float4*)&g_Wo[i] = make_float4(cvtf(v.x), cvtf(v.y), cvtf(v.z), cvtf(v.w));
}

// ============================================================================
// Kernel 0b: per-batch key compaction (sorted unmasked indices + count).
// ============================================================================
__global__ void build_idx(const int* __restrict__ mask) {
    __shared__ int wsum[33];
    const int b = blockIdx.x, tid = threadIdx.x;
    const int lane = tid & 31, w = tid >> 5;
    const int flag = mask[b * SS + tid] ? 0 : 1;   // 1 = unmasked (keep)
    unsigned bal = __ballot_sync(0xffffffffu, flag);
    int pre = __popc(bal & ((1u << lane) - 1u));
    if (lane == 0) wsum[w] = __popc(bal);
    __syncthreads();
    if (tid == 0) {
        int s = 0;
        for (int i = 0; i < 32; ++i) { int tt = wsum[i]; wsum[i] = s; s += tt; }
        wsum[32] = s;
        g_nb[b] = s;
    }
    __syncthreads();
    const int nb = wsum[32];
    if (tid >= nb) g_idx[b * SS + tid] = 0;          // pad slots -> row 0 (zeroed later)
    if (flag) g_idx[b * SS + wsum[w] + pre] = tid;   // distinct slots (< nb)
}

// ============================================================================
// Kernel 1: fused QKV projection (R12-identical). grid (8, 16, 8), 512 threads.
// ============================================================================
#define PP 68
#define PRJ_WS   (128 * PP)
#define PRJ_BIAS (128 * PP + 192 * PP)
#define PRJ_SMEM_F (PRJ_BIAS + 192)

__global__ __launch_bounds__(512) void proj_mma(
    const float* __restrict__ x,
    const float* __restrict__ Wq, const float* __restrict__ bq,
    const float* __restrict__ Wk, const float* __restrict__ bk,
    const float* __restrict__ Wv, const float* __restrict__ bv)
{
    extern __shared__ float sm[];
    float* xs = sm;
    float* ws = sm + PRJ_WS;
    float* sbias = sm + PRJ_BIAS;
    const uint32_t sb = smem_u32(sm);

    const int b = blockIdx.z, h = blockIdx.y, s0 = blockIdx.x * 128;
    const int tid = threadIdx.x, wid = tid >> 5, lane = tid & 31;
    const int g = lane >> 2, t = lane & 3;
    const int wr = wid & 3, wc = wid >> 2;
    const int r0 = wr * 32, c0 = wc * 48;

    for (int i = tid; i < 128 * 16; i += 512) {
        int r = i >> 4, c4 = (i & 15) << 2;
        cpa16(sb + (uint32_t)(r * PP + c4) * 4,
              &x[((size_t)(b * SS + s0 + r)) * DD + h * HD + c4]);
    }
    CP_COMMIT();

    {
        const float* Wsrc[3] = { Wq + (size_t)h * HD * HD, Wk + (size_t)h * HD * HD,
                                 Wv + (size_t)h * HD * HD };
        for (int i = tid; i < 3 * 4096; i += 512) {
            int w = i >> 12, r = i & 4095, d = r >> 6, e = r & 63;
            ws[(w * 64 + e) * PP + d] = cvtf(Wsrc[w][r]);
        }
        if (tid < 192) {
            int w = tid >> 6, e = tid & 63;
            const float* bsrc[3] = { bq, bk, bv };
            sbias[tid] = bsrc[w][h * HD + e];
        }
    }
    CP_WAIT(0);
    __syncthreads();
    for (int i = tid; i < 128 * 16; i += 512) {
        int r = i >> 4, c4 = (i & 15) << 2;
        float4 v = *(float4*)&xs[r * PP + c4];
        *(float4*)&xs[r * PP + c4] = make_float4(cvtf(v.x), cvtf(v.y), cvtf(v.z), cvtf(v.w));
    }
    __syncthreads();

    float acc[2][6][4] = {};
    #pragma unroll
    for (int kk = 0; kk < 8; ++kk) {
        uint32_t a0[4], a1[4];
        lda(a0, xs, PP, r0, kk * 8, g, t);
        lda(a1, xs, PP, r0 + 16, kk * 8, g, t);
        #pragma unroll
        for (int n = 0; n < 6; ++n) {
            uint32_t bb[2];
            ldb_nk(bb, ws, PP, c0 + n * 8, kk * 8, g, t);
            mma8(acc[0][n], a0, bb);
            mma8(acc[1][n], a1, bb);
        }
    }

    float* gdst[3] = { g_Q, g_K, g_V };
    #pragma unroll
    for (int m = 0; m < 2; ++m) {
        #pragma unroll
        for (int n = 0; n < 6; ++n) {
            int gcol = c0 + n * 8 + t * 2;
            int w = gcol >> 6, lcol = gcol & 63;
            float b0 = sbias[gcol], b1 = sbias[gcol + 1];
            int row = s0 + r0 + m * 16 + g;
            float* outp = gdst[w];
            size_t base0 = ((size_t)((b * HH + h) * SS + row)) * HD + lcol;
            size_t base1 = ((size_t)((b * HH + h) * SS + row + 8)) * HD + lcol;
            *(float2*)&outp[base0] = make_float2(cvtf(acc[m][n][0] + b0), cvtf(acc[m][n][1] + b1));
            *(float2*)&outp[base1] = make_float2(cvtf(acc[m][n][2] + b0), cvtf(acc[m][n][3] + b1));
        }
    }
}

// ============================================================================
// Kernel 2: flash attention over COMPACTED keys, 64-key double-buffered
// pipeline. grid (8, 16, 8), 128 threads, ~106.5KB smem -> 2 CTAs/SM.
// Per iteration: one cp.async group (K+V for 64 keys) waited with one
// CP_WAIT(1); no mid-iteration V wait; group i+2 issued into the freed buffer.
// Math bit-identical to R12 (same op order; skipped pad halves added exact 0).
// ============================================================================
#define PA  68
#define KB0 0
#define KB1 (64 * PA)
#define VB0 (2 * 64 * PA)
#define VB1 (3 * 64 * PA)
#define AO_Q (4 * 64 * PA)
#define AO_IDX (AO_Q + 128 * PA)
#define ATTN_F (AO_IDX + 512)
#define EXPC 0.18033688f   // 0.125 * log2(e)

static __device__ __forceinline__ void s_tile(float p[2][8][4], const float* Qs,
                                              const float* Ks, int r0, int g, int t) {
    #pragma unroll
    for (int m = 0; m < 2; ++m)
        #pragma unroll
        for (int n = 0; n < 8; ++n)
            #pragma unroll
            for (int j = 0; j < 4; ++j) p[m][n][j] = 0.f;
    #pragma unroll
    for (int kk = 0; kk < 8; ++kk) {
        uint32_t a0[4], a1[4];
        lda(a0, Qs, PA, r0, kk * 8, g, t);
        lda(a1, Qs, PA, r0 + 16, kk * 8, g, t);
        #pragma unroll
        for (int n = 0; n < 8; ++n) {
            uint32_t bb[2];
            ldb_nk(bb, Ks, PA, n * 8, kk * 8, g, t);
            mma8(p[0][n], a0, bb);
            mma8(p[1][n], a1, bb);
        }
    }
}

static __device__ __forceinline__ void exp_tile(float p[2][8][4], int colbase, int nb,
                                                float rs[2][2], int t) {
    #pragma unroll
    for (int m = 0; m < 2; ++m)
        #pragma unroll
        for (int n = 0; n < 8; ++n) {
            int col = colbase + n * 8 + t * 2;
            float mx = (col < nb) ? 1.f : 0.f;
            float my = (col + 1 < nb) ? 1.f : 0.f;
            p[m][n][0] = ex2f(p[m][n][0] * EXPC) * mx;
            p[m][n][1] = ex2f(p[m][n][1] * EXPC) * my;
            p[m][n][2] = ex2f(p[m][n][2] * EXPC) * mx;
            p[m][n][3] = ex2f(p[m][n][3] * EXPC) * my;
            rs[m][0] += p[m][n][0] + p[m][n][1];
            rs[m][1] += p[m][n][2] + p[m][n][3];
        }
}

static __device__ __forceinline__ void pv_tile(float o[2][8][4], const float p[2][8][4],
                                               const float* Vs, int g, int t) {
    #pragma unroll
    for (int kkp = 0; kkp < 8; ++kkp) {
        uint32_t A0[4] = { __float_as_uint(p[0][kkp][0]), __float_as_uint(p[0][kkp][2]),
                           __float_as_uint(p[0][kkp][1]), __float_as_uint(p[0][kkp][3]) };
        uint32_t A1[4] = { __float_as_uint(p[1][kkp][0]), __float_as_uint(p[1][kkp][2]),
                           __float_as_uint(p[1][kkp][1]), __float_as_uint(p[1][kkp][3]) };
        const float* vrow0 = Vs + (kkp * 8 + 2 * t) * PA;
        const float* vrow1 = vrow0 + PA;
        #pragma unroll
        for (int n = 0; n < 8; ++n) {
            uint32_t bb[2];
            bb[0] = __float_as_uint(vrow0[n * 8 + g]);
            bb[1] = __float_as_uint(vrow1[n * 8 + g]);
            mma8(o[0][n], A0, bb);
            mma8(o[1][n], A1, bb);
        }
    }
}

__global__ __launch_bounds__(128, 2) void attn_mma()
{
    extern __shared__ float sm[];
    float* Qs = sm + AO_Q;
    unsigned short* s_idx = (unsigned short*)(sm + AO_IDX);
    const uint32_t sb = smem_u32(sm);

    const int b = blockIdx.z, h = blockIdx.y, q0 = blockIdx.x * 128;
    const int tid = threadIdx.x, wid = tid >> 5, lane = tid & 31;
    const int g = lane >> 2, t = lane & 3;
    const int r0 = wid * 32;

    const size_t bh = (size_t)(b * HH + h) * SS * HD;
    const float* Qp = g_Q + bh;
    const float* Kp = g_K + bh;
    const float* Vp = g_V + bh;

    // indices + count first (cp.async sources depend on them)
    for (int i = tid; i < SS; i += 128)
        s_idx[i] = (unsigned short)g_idx[b * SS + i];
    const int nb = g_nb[b];
    const int nt = (nb + 63) >> 6;       // 64-key iterations
    __syncthreads();

    // issue one group per 64-key tile: K(it)+V(it) (+Q in group 0)
    auto issue = [&](int it, int buf) {
        const uint32_t kbo = buf ? KB1 : KB0;
        const uint32_t vbo = buf ? VB1 : VB0;
        for (int i = tid; i < 64 * 16; i += 128) {
            int r = i >> 4, c4 = (i & 15) << 2;
            int src = s_idx[it * 64 + r];
            cpa16(sb + (kbo + (uint32_t)(r * PA + c4)) * 4, &Kp[(size_t)src * HD + c4]);
            cpa16(sb + (vbo + (uint32_t)(r * PA + c4)) * 4, &Vp[(size_t)src * HD + c4]);
        }
    };

    issue(0, 0);
    for (int i = tid; i < 128 * 16; i += 128) {
        int r = i >> 4, c4 = (i & 15) << 2;
        cpa16(sb + (uint32_t)(AO_Q + r * PA + c4) * 4, &Qp[(size_t)(q0 + r) * HD + c4]);
    }
    CP_COMMIT();              // group 0: K0,V0,Q
    issue(1, 1);
    CP_COMMIT();              // group 1: K1,V1

    float o[2][8][4] = {};
    float rs[2][2] = {};
    float p[2][8][4];

    for (int it = 0; it < nt; ++it) {
        CP_WAIT(1);           // group it complete (group it+1 may fly)
        __syncthreads();

        const float* Kb = sm + ((it & 1) ? KB1 : KB0);
        const float* Vb = sm + ((it & 1) ? VB1 : VB0);

        s_tile(p, Qs, Kb, r0, g, t);
        exp_tile(p, it * 64, nb, rs, t);
        pv_tile(o, p, Vb, g, t);

        __syncthreads();      // all warps done reading this buffer
        if (it + 2 < nt) issue(it + 2, it & 1);
        CP_COMMIT();          // group it+2 (empty near tail; keeps accounting uniform)
    }

    // row sums: quad-reduce (cols 2t,2t+1 across 8 n-blocks -> full row)
    #pragma unroll
    for (int m = 0; m < 2; ++m)
        #pragma unroll
        for (int j = 0; j < 2; ++j) {
            rs[m][j] += __shfl_xor_sync(0xffffffffu, rs[m][j], 1);
            rs[m][j] += __shfl_xor_sync(0xffffffffu, rs[m][j], 2);
        }

    #pragma unroll
    for (int m = 0; m < 2; ++m) {
        const float inv0 = 1.0f / rs[m][0], inv1 = 1.0f / rs[m][1];
        const int row = q0 + r0 + m * 16 + g;
        #pragma unroll
        for (int n = 0; n < 8; ++n) {
            int col = n * 8 + t * 2;
            size_t base0 = ((size_t)(b * SS + row)) * DD + h * HD + col;
            size_t base1 = ((size_t)(b * SS + row + 8)) * DD + h * HD + col;
            *(float2*)&g_C[base0] = make_float2(cvtf(o[m][n][0] * inv0), cvtf(o[m][n][1] * inv0));
            *(float2*)&g_C[base1] = make_float2(cvtf(o[m][n][2] * inv1), cvtf(o[m][n][3] * inv1));
        }
    }
}

// ============================================================================
// Kernel 3: out-proj Y = C @ Wo^T + bo (R12-identical). grid (8, 64),
// 128 threads (4 warps), block 128x128, warp 64x64 (1.0 LDS/mma),
// double-buffered k-chunks of 32 (72KB smem -> 2 CTAs/SM).
// ============================================================================
#define PO 36
#define OB_STRIDE (2 * 128 * PO)

__global__ __launch_bounds__(128, 2) void outproj_mma(
    const float* __restrict__ bo, float* __restrict__ y)
{
    extern __shared__ float sm[];
    const uint32_t sb = smem_u32(sm);

    const int n0 = blockIdx.x * 128;
    const int m0 = blockIdx.y * 128;
    const int tid = threadIdx.x, wid = tid >> 5, lane = tid & 31;
    const int g = lane >> 2, t = lane & 3;
    const int wr = wid & 1, wc = wid >> 1;
    const int r0 = wr * 64, c0 = wc * 64;

    auto issue = [&](int ch, int buf) {
        const uint32_t bofs = (uint32_t)(buf * OB_STRIDE);
        for (int i = tid; i < 128 * 8; i += 128) {
            int r = i >> 3, c4 = (i & 7) << 2;
            cpa16(sb + (bofs + (uint32_t)(r * PO + c4)) * 4,
                  &g_C[(size_t)(m0 + r) * DD + ch * 32 + c4]);
            cpa16(sb + (bofs + (uint32_t)(128 * PO + r * PO + c4)) * 4,
                  &g_Wo[(size_t)(n0 + r) * DD + ch * 32 + c4]);
        }
        CP_COMMIT();
    };
    issue(0, 0);
    issue(1, 1);

    float acc[4][8][4] = {};
    for (int ch = 0; ch < 32; ++ch) {
        CP_WAIT(1);
        __syncthreads();
        const float* Cs = sm + (ch & 1) * OB_STRIDE;
        const float* Ws = Cs + 128 * PO;
        #pragma unroll
        for (int kk = 0; kk < 4; ++kk) {
            uint32_t a_[4][4];
            #pragma unroll
            for (int m = 0; m < 4; ++m)
                lda(a_[m], Cs, PO, r0 + m * 16, kk * 8, g, t);
            #pragma unroll
            for (int n = 0; n < 8; ++n) {
                uint32_t bb[2];
                ldb_nk(bb, Ws, PO, c0 + n * 8, kk * 8, g, t);
                #pragma unroll
                for (int m = 0; m < 4; ++m)
                    mma8(acc[m][n], a_[m], bb);
            }
        }
        __syncthreads();
        if (ch + 2 < 32) issue(ch + 2, ch & 1);
        else CP_COMMIT();
    }

    #pragma unroll
    for (int m = 0; m < 4; ++m) {
        #pragma unroll
        for (int n = 0; n < 8; ++n) {
            int col = c0 + n * 8 + t * 2;
            float b0 = bo[n0 + col], b1 = bo[n0 + col + 1];
            int row = m0 + r0 + m * 16 + g;
            size_t base0 = (size_t)row * DD + n0 + col;
            size_t base1 = (size_t)(row + 8) * DD + n0 + col;
            *(float2*)&y[base0] = make_float2(acc[m][n][0] + b0, acc[m][n][1] + b1);
            *(float2*)&y[base1] = make_float2(acc[m][n][2] + b0, acc[m][n][3] + b1);
        }
    }
}

// ============================================================================
extern "C" void kernel_launch(void* const* d_in, const int* in_sizes, int n_in,
                              void* d_out, int out_size)
{
    const float* x  = (const float*)d_in[0];
    const int* mk   = (const int*)d_in[1];
    const float* Wq = (const float*)d_in[2];
    const float* bq = (const float*)d_in[3];
    const float* Wk = (const float*)d_in[4];
    const float* bk = (const float*)d_in[5];
    const float* Wv = (const float*)d_in[6];
    const float* bv = (const float*)d_in[7];
    const float* Wo = (const float*)d_in[8];
    const float* bo = (const float*)d_in[9];
    float* y = (float*)d_out;

    const int smem_proj = PRJ_SMEM_F * 4;     // ~88 KB
    const int smem_attn = ATTN_F * 4;         // ~106.5 KB -> 2 CTAs/SM
    const int smem_out  = 2 * OB_STRIDE * 4;  // 72 KB -> 2 CTAs/SM
    cudaFuncSetAttribute(proj_mma, cudaFuncAttributeMaxDynamicSharedMemorySize, smem_proj);
    cudaFuncSetAttribute(attn_mma, cudaFuncAttributeMaxDynamicSharedMemorySize, smem_attn);
    cudaFuncSetAttribute(outproj_mma, cudaFuncAttributeMaxDynamicSharedMemorySize, smem_out);

    round_wo<<<DD * DD / 1024, 256>>>(Wo);
    build_idx<<<BB, SS>>>(mk);
    proj_mma<<<dim3(SS / 128, HH, BB), 512, smem_proj>>>(x, Wq, bq, Wk, bk, Wv, bv);
    attn_mma<<<dim3(SS / 128, HH, BB), 128, smem_attn>>>();
    outproj_mma<<<dim3(DD / 128, BB * SS / 128), 128, smem_out>>>(bo, y);
}

// round 16
// speedup vs baseline: 1.0913x; 1.0003x over previous
#include <cuda_runtime.h>
#include <cstdint>

#define BB 8
#define SS 1024
#define DD 1024
#define HH 16
#define HD 64

// Scratch (device globals). All contents tf32-rounded fp32 (rounded once, rna).
__device__ float g_K[BB*HH*SS*HD];
__device__ float g_V[BB*HH*SS*HD];
__device__ float g_C[(size_t)BB*SS*DD];
__device__ float g_Wo[DD*DD];
__device__ int   g_idx[BB*SS];   // per-batch compacted unmasked key indices
__device__ int   g_nb[BB];       // per-batch unmasked count

// ---------------- helpers ----------------
static __device__ __forceinline__ uint32_t cvt_tf32(float f) {
    uint32_t u; asm("cvt.rna.tf32.f32 %0, %1;" : "=r"(u) : "f"(f)); return u;
}
static __device__ __forceinline__ float cvtf(float f) { return __uint_as_float(cvt_tf32(f)); }
static __device__ __forceinline__ float ex2f(float x) {
    float y; asm("ex2.approx.f32 %0, %1;" : "=f"(y) : "f"(x)); return y;
}
static __device__ __forceinline__ void mma8(float* d, const uint32_t* a, const uint32_t* b) {
    asm volatile("mma.sync.aligned.m16n8k8.row.col.f32.tf32.tf32.f32 "
        "{%0,%1,%2,%3}, {%4,%5,%6,%7}, {%8,%9}, {%0,%1,%2,%3};"
        : "+f"(d[0]), "+f"(d[1]), "+f"(d[2]), "+f"(d[3])
        : "r"(a[0]), "r"(a[1]), "r"(a[2]), "r"(a[3]), "r"(b[0]), "r"(b[1]));
}
static __device__ __forceinline__ void lda(uint32_t* a, const float* s, int P,
                                           int r0, int k0, int g, int t) {
    a[0] = __float_as_uint(s[(r0 + g) * P + k0 + t]);
    a[1] = __float_as_uint(s[(r0 + g + 8) * P + k0 + t]);
    a[2] = __float_as_uint(s[(r0 + g) * P + k0 + t + 4]);
    a[3] = __float_as_uint(s[(r0 + g + 8) * P + k0 + t + 4]);
}
static __device__ __forceinline__ void ldb_nk(uint32_t* b, const float* s, int P,
                                              int n0, int k0, int g, int t) {
    b[0] = __float_as_uint(s[(n0 + g) * P + k0 + t]);
    b[1] = __float_as_uint(s[(n0 + g) * P + k0 + t + 4]);
}
static __device__ __forceinline__ uint32_t smem_u32(const void* p) {
    uint32_t a;
    asm("{ .reg .u64 t; cvta.to.shared.u64 t, %1; cvt.u32.u64 %0, t; }" : "=r"(a) : "l"(p));
    return a;
}
static __device__ __forceinline__ void cpa16(uint32_t dst, const void* src) {
    asm volatile("cp.async.ca.shared.global [%0], [%1], 16;" :: "r"(dst), "l"(src));
}
#define CP_COMMIT() asm volatile("cp.async.commit_group;" ::: "memory")
#define CP_WAIT(n)  asm volatile("cp.async.wait_group %0;" :: "n"(n) : "memory")

// ============================================================================
// Kernel 0a: tf32-round Wo (once).
// ============================================================================
__global__ void round_wo(const float* __restrict__ Wo) {
    int i = (blockIdx.x * 256 + threadIdx.x) * 4;
    float4 v = *(const float4*)&Wo[i];
    *(float4*)&g_Wo[i] = make_float4(cvtf(v.x), cvtf(v.y), cvtf(v.z), cvtf(v.w));
}

// ============================================================================
// Kernel 0b: per-batch key compaction (sorted unmasked indices + count).
// ============================================================================
__global__ void build_idx(const int* __restrict__ mask) {
    __shared__ int wsum[33];
    const int b = blockIdx.x, tid = threadIdx.x;
    const int lane = tid & 31, w = tid >> 5;
    const int flag = mask[b * SS + tid] ? 0 : 1;   // 1 = unmasked (keep)
    unsigned bal = __ballot_sync(0xffffffffu, flag);
    int pre = __popc(bal & ((1u << lane) - 1u));
    if (lane == 0) wsum[w] = __popc(bal);
    __syncthreads();
    if (tid == 0) {
        int s = 0;
        for (int i = 0; i < 32; ++i) { int tt = wsum[i]; wsum[i] = s; s += tt; }
        wsum[32] = s;
        g_nb[b] = s;
    }
    __syncthreads();
    const int nb = wsum[32];
    if (tid >= nb) g_idx[b * SS + tid] = 0;
    if (flag) g_idx[b * SS + wsum[w] + pre] = tid;
}

// ============================================================================
// Kernel 1: K/V projection (proj minus Q). grid (8, 16, 8), 512 threads.
// [128 rows x 64] x [64 x 128]  (B = [Wk^T | Wv^T]). Warp tile 32x32.
// ============================================================================
#define PP 68
#define PRJ_WS   (128 * PP)
#define PRJ_BIAS (PRJ_WS + 128 * PP)
#define PRJ_SMEM_F (PRJ_BIAS + 128)

__global__ __launch_bounds__(512) void kv_proj(
    const float* __restrict__ x,
    const float* __restrict__ Wk, const float* __restrict__ bk,
    const float* __restrict__ Wv, const float* __restrict__ bv)
{
    extern __shared__ float sm[];
    float* xs = sm;
    float* ws = sm + PRJ_WS;
    float* sbias = sm + PRJ_BIAS;
    const uint32_t sb = smem_u32(sm);

    const int b = blockIdx.z, h = blockIdx.y, s0 = blockIdx.x * 128;
    const int tid = threadIdx.x, wid = tid >> 5, lane = tid & 31;
    const int g = lane >> 2, t = lane & 3;
    const int wr = wid & 3, wc = wid >> 2;
    const int r0 = wr * 32, c0 = wc * 32;

    for (int i = tid; i < 128 * 16; i += 512) {
        int r = i >> 4, c4 = (i & 15) << 2;
        cpa16(sb + (uint32_t)(r * PP + c4) * 4,
              &x[((size_t)(b * SS + s0 + r)) * DD + h * HD + c4]);
    }
    CP_COMMIT();

    {
        const float* Wsrc[2] = { Wk + (size_t)h * HD * HD, Wv + (size_t)h * HD * HD };
        for (int i = tid; i < 2 * 4096; i += 512) {
            int w = i >> 12, r = i & 4095, d = r >> 6, e = r & 63;
            ws[(w * 64 + e) * PP + d] = cvtf(Wsrc[w][r]);
        }
        if (tid < 128) {
            int w = tid >> 6, e = tid & 63;
            const float* bsrc[2] = { bk, bv };
            sbias[tid] = bsrc[w][h * HD + e];
        }
    }
    CP_WAIT(0);
    __syncthreads();
    for (int i = tid; i < 128 * 16; i += 512) {
        int r = i >> 4, c4 = (i & 15) << 2;
        float4 v = *(float4*)&xs[r * PP + c4];
        *(float4*)&xs[r * PP + c4] = make_float4(cvtf(v.x), cvtf(v.y), cvtf(v.z), cvtf(v.w));
    }
    __syncthreads();

    float acc[2][4][4] = {};
    #pragma unroll
    for (int kk = 0; kk < 8; ++kk) {
        uint32_t a0[4], a1[4];
        lda(a0, xs, PP, r0, kk * 8, g, t);
        lda(a1, xs, PP, r0 + 16, kk * 8, g, t);
        #pragma unroll
        for (int n = 0; n < 4; ++n) {
            uint32_t bb[2];
            ldb_nk(bb, ws, PP, c0 + n * 8, kk * 8, g, t);
            mma8(acc[0][n], a0, bb);
            mma8(acc[1][n], a1, bb);
        }
    }

    float* gdst[2] = { g_K, g_V };
    #pragma unroll
    for (int m = 0; m < 2; ++m) {
        #pragma unroll
        for (int n = 0; n < 4; ++n) {
            int gcol = c0 + n * 8 + t * 2;
            int w = gcol >> 6, lcol = gcol & 63;
            float b0 = sbias[gcol], b1 = sbias[gcol + 1];
            int row = s0 + r0 + m * 16 + g;
            float* outp = gdst[w];
            size_t base0 = ((size_t)((b * HH + h) * SS + row)) * HD + lcol;
            size_t base1 = ((size_t)((b * HH + h) * SS + row + 8)) * HD + lcol;
            *(float2*)&outp[base0] = make_float2(cvtf(acc[m][n][0] + b0), cvtf(acc[m][n][1] + b1));
            *(float2*)&outp[base1] = make_float2(cvtf(acc[m][n][2] + b0), cvtf(acc[m][n][3] + b1));
        }
    }
}

// ============================================================================
// Kernel 2: flash attention with FUSED Q projection, compacted keys,
// 64-key double-buffered K/V pipeline. grid (8, 16, 8), 128 threads,
// ~71.7KB smem -> 2 CTAs/SM (regs-bound).
// Q computed in-kernel (x tile + Wq^T overlaid on K/V buffers pre-loop),
// kept in registers as PERMUTED D-frags (d0,d2,d1,d3); S uses the hw-k remap
// (slot t <-> logical k=2t) so K B-frags are contiguous float2 loads.
// ============================================================================
#define PA  68
#define KB0 0
#define KB1 (64 * PA)
#define VB0 (2 * 64 * PA)
#define VB1 (3 * 64 * PA)
#define AO_IDX (4 * 64 * PA)
#define ATTN_F (AO_IDX + 512)
#define EXPC 0.18033688f   // 0.125 * log2(e)

static __device__ __forceinline__ void exp_tile(float p[2][8][4], int colbase, int nb,
                                                float rs[2][2], int t) {
    #pragma unroll
    for (int m = 0; m < 2; ++m)
        #pragma unroll
        for (int n = 0; n < 8; ++n) {
            int col = colbase + n * 8 + t * 2;
            float mx = (col < nb) ? 1.f : 0.f;
            float my = (col + 1 < nb) ? 1.f : 0.f;
            p[m][n][0] = ex2f(p[m][n][0] * EXPC) * mx;
            p[m][n][1] = ex2f(p[m][n][1] * EXPC) * my;
            p[m][n][2] = ex2f(p[m][n][2] * EXPC) * mx;
            p[m][n][3] = ex2f(p[m][n][3] * EXPC) * my;
            rs[m][0] += p[m][n][0] + p[m][n][1];
            rs[m][1] += p[m][n][2] + p[m][n][3];
        }
}

static __device__ __forceinline__ void pv_tile(float o[2][8][4], const float p[2][8][4],
                                               const float* Vs, int g, int t) {
    #pragma unroll
    for (int kkp = 0; kkp < 8; ++kkp) {
        uint32_t A0[4] = { __float_as_uint(p[0][kkp][0]), __float_as_uint(p[0][kkp][2]),
                           __float_as_uint(p[0][kkp][1]), __float_as_uint(p[0][kkp][3]) };
        uint32_t A1[4] = { __float_as_uint(p[1][kkp][0]), __float_as_uint(p[1][kkp][2]),
                           __float_as_uint(p[1][kkp][1]), __float_as_uint(p[1][kkp][3]) };
        const float* vrow0 = Vs + (kkp * 8 + 2 * t) * PA;
        const float* vrow1 = vrow0 + PA;
        #pragma unroll
        for (int n = 0; n < 8; ++n) {
            uint32_t bb[2];
            bb[0] = __float_as_uint(vrow0[n * 8 + g]);
            bb[1] = __float_as_uint(vrow1[n * 8 + g]);
            mma8(o[0][n], A0, bb);
            mma8(o[1][n], A1, bb);
        }
    }
}

__global__ __launch_bounds__(128, 2) void attn_mma(
    const float* __restrict__ x,
    const float* __restrict__ Wq, const float* __restrict__ bq)
{
    extern __shared__ float sm[];
    float* xs = sm;               // 128 x PA (overlays KB0+KB1 pre-loop)
    float* wqs = sm + VB0;        // 64 x PA (overlays VB0 pre-loop)
    unsigned short* s_idx = (unsigned short*)(sm + AO_IDX);
    const uint32_t sb = smem_u32(sm);

    const int b = blockIdx.z, h = blockIdx.y, q0 = blockIdx.x * 128;
    const int tid = threadIdx.x, wid = tid >> 5, lane = tid & 31;
    const int g = lane >> 2, t = lane & 3;
    const int r0 = wid * 32;

    const size_t bh = (size_t)(b * HH + h) * SS * HD;
    const float* Kp = g_K + bh;
    const float* Vp = g_V + bh;

    // ---- stage x (cp.async) + Wq^T (scalar) + idx ----
    for (int i = tid; i < 128 * 16; i += 128) {
        int r = i >> 4, c4 = (i & 15) << 2;
        cpa16(sb + (uint32_t)(r * PA + c4) * 4,
              &x[((size_t)(b * SS + q0 + r)) * DD + h * HD + c4]);
    }
    CP_COMMIT();
    {
        const float* Wsrc = Wq + (size_t)h * HD * HD;
        for (int i = tid; i < 4096; i += 128) {
            int d = i >> 6, e = i & 63;
            wqs[e * PA + d] = cvtf(Wsrc[i]);
        }
    }
    for (int i = tid; i < SS; i += 128)
        s_idx[i] = (unsigned short)g_idx[b * SS + i];
    const int nb = g_nb[b];
    const int nt = (nb + 63) >> 6;
    CP_WAIT(0);
    __syncthreads();
    // in-place round x
    for (int i = tid; i < 128 * 16; i += 128) {
        int r = i >> 4, c4 = (i & 15) << 2;
        float4 v = *(float4*)&xs[r * PA + c4];
        *(float4*)&xs[r * PA + c4] = make_float4(cvtf(v.x), cvtf(v.y), cvtf(v.z), cvtf(v.w));
    }
    __syncthreads();

    // ---- Q = x @ Wq^T + bq, kept in regs as permuted D-frags ----
    float q[2][8][4];   // [m][kcol-group][perm frag]
    {
        float qa[2][8][4] = {};
        #pragma unroll
        for (int kk = 0; kk < 8; ++kk) {
            uint32_t a0[4], a1[4];
            lda(a0, xs, PA, r0, kk * 8, g, t);
            lda(a1, xs, PA, r0 + 16, kk * 8, g, t);
            #pragma unroll
            for (int n = 0; n < 8; ++n) {
                uint32_t bb[2];
                ldb_nk(bb, wqs, PA, n * 8, kk * 8, g, t);
                mma8(qa[0][n], a0, bb);
                mma8(qa[1][n], a1, bb);
            }
        }
        #pragma unroll
        for (int m = 0; m < 2; ++m)
            #pragma unroll
            for (int n = 0; n < 8; ++n) {
                float b0 = bq[h * HD + n * 8 + t * 2];
                float b1 = bq[h * HD + n * 8 + t * 2 + 1];
                // permuted order: (d0, d2, d1, d3)
                q[m][n][0] = cvtf(qa[m][n][0] + b0);
                q[m][n][1] = cvtf(qa[m][n][2] + b0);
                q[m][n][2] = cvtf(qa[m][n][1] + b1);
                q[m][n][3] = cvtf(qa[m][n][3] + b1);
            }
    }
    __syncthreads();   // done reading xs/wqs; K/V buffers may be overwritten

    // ---- K/V pipeline ----
    auto issue = [&](int it, int buf) {
        const uint32_t kbo = buf ? KB1 : KB0;
        const uint32_t vbo = buf ? VB1 : VB0;
        for (int i = tid; i < 64 * 16; i += 128) {
            int r = i >> 4, c4 = (i & 15) << 2;
            int src = s_idx[it * 64 + r];
            cpa16(sb + (kbo + (uint32_t)(r * PA + c4)) * 4, &Kp[(size_t)src * HD + c4]);
            cpa16(sb + (vbo + (uint32_t)(r * PA + c4)) * 4, &Vp[(size_t)src * HD + c4]);
        }
        CP_COMMIT();
    };
    issue(0, 0);
    issue(1, 1);

    float o[2][8][4] = {};
    float rs[2][2] = {};
    float p[2][8][4];

    for (int it = 0; it < nt; ++it) {
        CP_WAIT(1);
        __syncthreads();

        const float* Kb = sm + ((it & 1) ? KB1 : KB0);
        const float* Vb = sm + ((it & 1) ? VB1 : VB0);

        // S = Q K^T with register A-frags (hw slot t <-> logical k=2t):
        // B frag = K[n+g][kk*8 + 2t], K[n+g][kk*8 + 2t + 1] (contiguous float2)
        #pragma unroll
        for (int m = 0; m < 2; ++m)
            #pragma unroll
            for (int n = 0; n < 8; ++n)
                #pragma unroll
                for (int j = 0; j < 4; ++j) p[m][n][j] = 0.f;
        #pragma unroll
        for (int kk = 0; kk < 8; ++kk) {
            const uint32_t* A0 = (const uint32_t*)q[0][kk];
            const uint32_t* A1 = (const uint32_t*)q[1][kk];
            #pragma unroll
            for (int n = 0; n < 8; ++n) {
                float2 kv = *(const float2*)&Kb[(n * 8 + g) * PA + kk * 8 + 2 * t];
                uint32_t bb[2] = { __float_as_uint(kv.x), __float_as_uint(kv.y) };
                mma8(p[0][n], A0, bb);
                mma8(p[1][n], A1, bb);
            }
        }

        exp_tile(p, it * 64, nb, rs, t);
        pv_tile(o, p, Vb, g, t);

        __syncthreads();
        if (it + 2 < nt) issue(it + 2, it & 1);
        else CP_COMMIT();
    }

    #pragma unroll
    for (int m = 0; m < 2; ++m)
        #pragma unroll
        for (int j = 0; j < 2; ++j) {
            rs[m][j] += __shfl_xor_sync(0xffffffffu, rs[m][j], 1);
            rs[m][j] += __shfl_xor_sync(0xffffffffu, rs[m][j], 2);
        }

    #pragma unroll
    for (int m = 0; m < 2; ++m) {
        const float inv0 = 1.0f / rs[m][0], inv1 = 1.0f / rs[m][1];
        const int row = q0 + r0 + m * 16 + g;
        #pragma unroll
        for (int n = 0; n < 8; ++n) {
            int col = n * 8 + t * 2;
            size_t base0 = ((size_t)(b * SS + row)) * DD + h * HD + col;
            size_t base1 = ((size_t)(b * SS + row + 8)) * DD + h * HD + col;
            *(float2*)&g_C[base0] = make_float2(cvtf(o[m][n][0] * inv0), cvtf(o[m][n][1] * inv0));
            *(float2*)&g_C[base1] = make_float2(cvtf(o[m][n][2] * inv1), cvtf(o[m][n][3] * inv1));
        }
    }
}

// ============================================================================
// Kernel 3: out-proj Y = C @ Wo^T + bo (R12-identical). grid (8, 64),
// 128 threads, block 128x128, warp 64x64, double-buffered k-chunks of 32.
// ============================================================================
#define PO 36
#define OB_STRIDE (2 * 128 * PO)

__global__ __launch_bounds__(128, 2) void outproj_mma(
    const float* __restrict__ bo, float* __restrict__ y)
{
    extern __shared__ float sm[];
    const uint32_t sb = smem_u32(sm);

    const int n0 = blockIdx.x * 128;
    const int m0 = blockIdx.y * 128;
    const int tid = threadIdx.x, wid = tid >> 5, lane = tid & 31;
    const int g = lane >> 2, t = lane & 3;
    const int wr = wid & 1, wc = wid >> 1;
    const int r0 = wr * 64, c0 = wc * 64;

    auto issue = [&](int ch, int buf) {
        const uint32_t bofs = (uint32_t)(buf * OB_STRIDE);
        for (int i = tid; i < 128 * 8; i += 128) {
            int r = i >> 3, c4 = (i & 7) << 2;
            cpa16(sb + (bofs + (uint32_t)(r * PO + c4)) * 4,
                  &g_C[(size_t)(m0 + r) * DD + ch * 32 + c4]);
            cpa16(sb + (bofs + (uint32_t)(128 * PO + r * PO + c4)) * 4,
                  &g_Wo[(size_t)(n0 + r) * DD + ch * 32 + c4]);
        }
        CP_COMMIT();
    };
    issue(0, 0);
    issue(1, 1);

    float acc[4][8][4] = {};
    for (int ch = 0; ch < 32; ++ch) {
        CP_WAIT(1);
        __syncthreads();
        const float* Cs = sm + (ch & 1) * OB_STRIDE;
        const float* Ws = Cs + 128 * PO;
        #pragma unroll
        for (int kk = 0; kk < 4; ++kk) {
            uint32_t a_[4][4];
            #pragma unroll
            for (int m = 0; m < 4; ++m)
                lda(a_[m], Cs, PO, r0 + m * 16, kk * 8, g, t);
            #pragma unroll
            for (int n = 0; n < 8; ++n) {
                uint32_t bb[2];
                ldb_nk(bb, Ws, PO, c0 + n * 8, kk * 8, g, t);
                #pragma unroll
                for (int m = 0; m < 4; ++m)
                    mma8(acc[m][n], a_[m], bb);
            }
        }
        __syncthreads();
        if (ch + 2 < 32) issue(ch + 2, ch & 1);
        else CP_COMMIT();
    }

    #pragma unroll
    for (int m = 0; m < 4; ++m) {
        #pragma unroll
        for (int n = 0; n < 8; ++n) {
            int col = c0 + n * 8 + t * 2;
            float b0 = bo[n0 + col], b1 = bo[n0 + col + 1];
            int row = m0 + r0 + m * 16 + g;
            size_t base0 = (size_t)row * DD + n0 + col;
            size_t base1 = (size_t)(row + 8) * DD + n0 + col;
            *(float2*)&y[base0] = make_float2(acc[m][n][0] + b0, acc[m][n][1] + b1);
            *(float2*)&y[base1] = make_float2(acc[m][n][2] + b0, acc[m][n][3] + b1);
        }
    }
}

// ============================================================================
extern "C" void kernel_launch(void* const* d_in, const int* in_sizes, int n_in,
                              void* d_out, int out_size)
{
    const float* x  = (const float*)d_in[0];
    const int* mk   = (const int*)d_in[1];
    const float* Wq = (const float*)d_in[2];
    const float* bq = (const float*)d_in[3];
    const float* Wk = (const float*)d_in[4];
    const float* bk = (const float*)d_in[5];
    const float* Wv = (const float*)d_in[6];
    const float* bv = (const float*)d_in[7];
    const float* Wo = (const float*)d_in[8];
    const float* bo = (const float*)d_in[9];
    float* y = (float*)d_out;

    const int smem_proj = PRJ_SMEM_F * 4;     // ~70 KB
    const int smem_attn = ATTN_F * 4;         // ~71.7 KB
    const int smem_out  = 2 * OB_STRIDE * 4;  // 72 KB
    cudaFuncSetAttribute(kv_proj, cudaFuncAttributeMaxDynamicSharedMemorySize, smem_proj);
    cudaFuncSetAttribute(attn_mma, cudaFuncAttributeMaxDynamicSharedMemorySize, smem_attn);
    cudaFuncSetAttribute(outproj_mma, cudaFuncAttributeMaxDynamicSharedMemorySize, smem_out);

    round_wo<<<DD * DD / 1024, 256>>>(Wo);
    build_idx<<<BB, SS>>>(mk);
    kv_proj<<<dim3(SS / 128, HH, BB), 512, smem_proj>>>(x, Wk, bk, Wv, bv);
    attn_mma<<<dim3(SS / 128, HH, BB), 128, smem_attn>>>(x, Wq, bq);
    outproj_mma<<<dim3(DD / 128, BB * SS / 128), 128, smem_out>>>(bo, y);
}

// round 17
// speedup vs baseline: 1.1236x; 1.0296x over previous
#include <cuda_runtime.h>
#include <cstdint>

#define BB 8
#define SS 1024
#define DD 1024
#define HH 16
#define HD 64

// Scratch (device globals). All contents tf32-rounded fp32 (rounded once, rna).
__device__ float g_Q[BB*HH*SS*HD];
__device__ float g_K[BB*HH*SS*HD];
__device__ float g_V[BB*HH*SS*HD];
__device__ float g_C[(size_t)BB*SS*DD];
__device__ float g_Wo[DD*DD];
__device__ int   g_idx[BB*SS];   // per-batch compacted unmasked key indices
__device__ int   g_nb[BB];       // per-batch unmasked count

// ---------------- helpers ----------------
static __device__ __forceinline__ uint32_t cvt_tf32(float f) {
    uint32_t u; asm("cvt.rna.tf32.f32 %0, %1;" : "=r"(u) : "f"(f)); return u;
}
static __device__ __forceinline__ float cvtf(float f) { return __uint_as_float(cvt_tf32(f)); }
static __device__ __forceinline__ float ex2f(float x) {
    float y; asm("ex2.approx.f32 %0, %1;" : "=f"(y) : "f"(x)); return y;
}
static __device__ __forceinline__ void mma8(float* d, const uint32_t* a, const uint32_t* b) {
    asm volatile("mma.sync.aligned.m16n8k8.row.col.f32.tf32.tf32.f32 "
        "{%0,%1,%2,%3}, {%4,%5,%6,%7}, {%8,%9}, {%0,%1,%2,%3};"
        : "+f"(d[0]), "+f"(d[1]), "+f"(d[2]), "+f"(d[3])
        : "r"(a[0]), "r"(a[1]), "r"(a[2]), "r"(a[3]), "r"(b[0]), "r"(b[1]));
}
static __device__ __forceinline__ void lda(uint32_t* a, const float* s, int P,
                                           int r0, int k0, int g, int t) {
    a[0] = __float_as_uint(s[(r0 + g) * P + k0 + t]);
    a[1] = __float_as_uint(s[(r0 + g + 8) * P + k0 + t]);
    a[2] = __float_as_uint(s[(r0 + g) * P + k0 + t + 4]);
    a[3] = __float_as_uint(s[(r0 + g + 8) * P + k0 + t + 4]);
}
static __device__ __forceinline__ void ldb_nk(uint32_t* b, const float* s, int P,
                                              int n0, int k0, int g, int t) {
    b[0] = __float_as_uint(s[(n0 + g) * P + k0 + t]);
    b[1] = __float_as_uint(s[(n0 + g) * P + k0 + t + 4]);
}
static __device__ __forceinline__ uint32_t smem_u32(const void* p) {
    uint32_t a;
    asm("{ .reg .u64 t; cvta.to.shared.u64 t, %1; cvt.u32.u64 %0, t; }" : "=r"(a) : "l"(p));
    return a;
}
static __device__ __forceinline__ void cpa16(uint32_t dst, const void* src) {
    asm volatile("cp.async.ca.shared.global [%0], [%1], 16;" :: "r"(dst), "l"(src));
}
#define CP_COMMIT() asm volatile("cp.async.commit_group;" ::: "memory")
#define CP_WAIT(n)  asm volatile("cp.async.wait_group %0;" :: "n"(n) : "memory")

// ============================================================================
// Kernel 0a: tf32-round Wo (once).
// ============================================================================
__global__ void round_wo(const float* __restrict__ Wo) {
    int i = (blockIdx.x * 256 + threadIdx.x) * 4;
    float4 v = *(const float4*)&Wo[i];
    *(float4*)&g_Wo[i] = make_float4(cvtf(v.x), cvtf(v.y), cvtf(v.z), cvtf(v.w));
}

// ============================================================================
// Kernel 0b: per-batch key compaction (sorted unmasked indices + count).
// ============================================================================
__global__ void build_idx(const int* __restrict__ mask) {
    __shared__ int wsum[33];
    const int b = blockIdx.x, tid = threadIdx.x;
    const int lane = tid & 31, w = tid >> 5;
    const int flag = mask[b * SS + tid] ? 0 : 1;   // 1 = unmasked (keep)
    unsigned bal = __ballot_sync(0xffffffffu, flag);
    int pre = __popc(bal & ((1u << lane) - 1u));
    if (lane == 0) wsum[w] = __popc(bal);
    __syncthreads();
    if (tid == 0) {
        int s = 0;
        for (int i = 0; i < 32; ++i) { int tt = wsum[i]; wsum[i] = s; s += tt; }
        wsum[32] = s;
        g_nb[b] = s;
    }
    __syncthreads();
    const int nb = wsum[32];
    if (tid >= nb) g_idx[b * SS + tid] = 0;
    if (flag) g_idx[b * SS + wsum[w] + pre] = tid;
}

// ============================================================================
// Kernel 1: fused QKV projection (R12-identical). grid (8, 16, 8), 512 threads.
// ============================================================================
#define PP 68
#define PRJ_WS   (128 * PP)
#define PRJ_BIAS (128 * PP + 192 * PP)
#define PRJ_SMEM_F (PRJ_BIAS + 192)

__global__ __launch_bounds__(512) void proj_mma(
    const float* __restrict__ x,
    const float* __restrict__ Wq, const float* __restrict__ bq,
    const float* __restrict__ Wk, const float* __restrict__ bk,
    const float* __restrict__ Wv, const float* __restrict__ bv)
{
    extern __shared__ float sm[];
    float* xs = sm;
    float* ws = sm + PRJ_WS;
    float* sbias = sm + PRJ_BIAS;
    const uint32_t sb = smem_u32(sm);

    const int b = blockIdx.z, h = blockIdx.y, s0 = blockIdx.x * 128;
    const int tid = threadIdx.x, wid = tid >> 5, lane = tid & 31;
    const int g = lane >> 2, t = lane & 3;
    const int wr = wid & 3, wc = wid >> 2;
    const int r0 = wr * 32, c0 = wc * 48;

    for (int i = tid; i < 128 * 16; i += 512) {
        int r = i >> 4, c4 = (i & 15) << 2;
        cpa16(sb + (uint32_t)(r * PP + c4) * 4,
              &x[((size_t)(b * SS + s0 + r)) * DD + h * HD + c4]);
    }
    CP_COMMIT();

    {
        const float* Wsrc[3] = { Wq + (size_t)h * HD * HD, Wk + (size_t)h * HD * HD,
                                 Wv + (size_t)h * HD * HD };
        for (int i = tid; i < 3 * 4096; i += 512) {
            int w = i >> 12, r = i & 4095, d = r >> 6, e = r & 63;
            ws[(w * 64 + e) * PP + d] = cvtf(Wsrc[w][r]);
        }
        if (tid < 192) {
            int w = tid >> 6, e = tid & 63;
            const float* bsrc[3] = { bq, bk, bv };
            sbias[tid] = bsrc[w][h * HD + e];
        }
    }
    CP_WAIT(0);
    __syncthreads();
    for (int i = tid; i < 128 * 16; i += 512) {
        int r = i >> 4, c4 = (i & 15) << 2;
        float4 v = *(float4*)&xs[r * PP + c4];
        *(float4*)&xs[r * PP + c4] = make_float4(cvtf(v.x), cvtf(v.y), cvtf(v.z), cvtf(v.w));
    }
    __syncthreads();

    float acc[2][6][4] = {};
    #pragma unroll
    for (int kk = 0; kk < 8; ++kk) {
        uint32_t a0[4], a1[4];
        lda(a0, xs, PP, r0, kk * 8, g, t);
        lda(a1, xs, PP, r0 + 16, kk * 8, g, t);
        #pragma unroll
        for (int n = 0; n < 6; ++n) {
            uint32_t bb[2];
            ldb_nk(bb, ws, PP, c0 + n * 8, kk * 8, g, t);
            mma8(acc[0][n], a0, bb);
            mma8(acc[1][n], a1, bb);
        }
    }

    float* gdst[3] = { g_Q, g_K, g_V };
    #pragma unroll
    for (int m = 0; m < 2; ++m) {
        #pragma unroll
        for (int n = 0; n < 6; ++n) {
            int gcol = c0 + n * 8 + t * 2;
            int w = gcol >> 6, lcol = gcol & 63;
            float b0 = sbias[gcol], b1 = sbias[gcol + 1];
            int row = s0 + r0 + m * 16 + g;
            float* outp = gdst[w];
            size_t base0 = ((size_t)((b * HH + h) * SS + row)) * HD + lcol;
            size_t base1 = ((size_t)((b * HH + h) * SS + row + 8)) * HD + lcol;
            *(float2*)&outp[base0] = make_float2(cvtf(acc[m][n][0] + b0), cvtf(acc[m][n][1] + b1));
            *(float2*)&outp[base1] = make_float2(cvtf(acc[m][n][2] + b0), cvtf(acc[m][n][3] + b1));
        }
    }
}

// ============================================================================
// Kernel 2: flash attention, compacted keys, 64-key double-buffered K/V
// pipeline, REGISTER-RESIDENT Q. grid (8, 16, 8), 128 threads,
// ~71.7KB smem -> 2 CTAs/SM.
// Q A-frags loaded once per thread directly from g_Q (LDG.64, overlapping the
// first K/V cp.async groups) in hw-k-remap order: slot t <-> logical dim 2t.
// S B-frags are contiguous float2 K loads (validated in R16, rel_err moved
// only at 1e-6). PV unchanged (P D-frag reuse via permuted V rows).
// ============================================================================
#define PA  68
#define KB0 0
#define KB1 (64 * PA)
#define VB0 (2 * 64 * PA)
#define VB1 (3 * 64 * PA)
#define AO_IDX (4 * 64 * PA)
#define ATTN_F (AO_IDX + 512)
#define EXPC 0.18033688f   // 0.125 * log2(e)

static __device__ __forceinline__ void exp_tile(float p[2][8][4], int colbase, int nb,
                                                float rs[2][2], int t) {
    #pragma unroll
    for (int m = 0; m < 2; ++m)
        #pragma unroll
        for (int n = 0; n < 8; ++n) {
            int col = colbase + n * 8 + t * 2;
            float mx = (col < nb) ? 1.f : 0.f;
            float my = (col + 1 < nb) ? 1.f : 0.f;
            p[m][n][0] = ex2f(p[m][n][0] * EXPC) * mx;
            p[m][n][1] = ex2f(p[m][n][1] * EXPC) * my;
            p[m][n][2] = ex2f(p[m][n][2] * EXPC) * mx;
            p[m][n][3] = ex2f(p[m][n][3] * EXPC) * my;
            rs[m][0] += p[m][n][0] + p[m][n][1];
            rs[m][1] += p[m][n][2] + p[m][n][3];
        }
}

static __device__ __forceinline__ void pv_tile(float o[2][8][4], const float p[2][8][4],
                                               const float* Vs, int g, int t) {
    #pragma unroll
    for (int kkp = 0; kkp < 8; ++kkp) {
        uint32_t A0[4] = { __float_as_uint(p[0][kkp][0]), __float_as_uint(p[0][kkp][2]),
                           __float_as_uint(p[0][kkp][1]), __float_as_uint(p[0][kkp][3]) };
        uint32_t A1[4] = { __float_as_uint(p[1][kkp][0]), __float_as_uint(p[1][kkp][2]),
                           __float_as_uint(p[1][kkp][1]), __float_as_uint(p[1][kkp][3]) };
        const float* vrow0 = Vs + (kkp * 8 + 2 * t) * PA;
        const float* vrow1 = vrow0 + PA;
        #pragma unroll
        for (int n = 0; n < 8; ++n) {
            uint32_t bb[2];
            bb[0] = __float_as_uint(vrow0[n * 8 + g]);
            bb[1] = __float_as_uint(vrow1[n * 8 + g]);
            mma8(o[0][n], A0, bb);
            mma8(o[1][n], A1, bb);
        }
    }
}

__global__ __launch_bounds__(128, 2) void attn_mma()
{
    extern __shared__ float sm[];
    unsigned short* s_idx = (unsigned short*)(sm + AO_IDX);
    const uint32_t sb = smem_u32(sm);

    const int b = blockIdx.z, h = blockIdx.y, q0 = blockIdx.x * 128;
    const int tid = threadIdx.x, wid = tid >> 5, lane = tid & 31;
    const int g = lane >> 2, t = lane & 3;
    const int r0 = wid * 32;

    const size_t bh = (size_t)(b * HH + h) * SS * HD;
    const float* Qp = g_Q + bh;
    const float* Kp = g_K + bh;
    const float* Vp = g_V + bh;

    // indices + count first (cp.async sources depend on them)
    for (int i = tid; i < SS; i += 128)
        s_idx[i] = (unsigned short)g_idx[b * SS + i];
    const int nb = g_nb[b];
    const int nt = (nb + 63) >> 6;
    __syncthreads();

    auto issue = [&](int it, int buf) {
        const uint32_t kbo = buf ? KB1 : KB0;
        const uint32_t vbo = buf ? VB1 : VB0;
        for (int i = tid; i < 64 * 16; i += 128) {
            int r = i >> 4, c4 = (i & 15) << 2;
            int src = s_idx[it * 64 + r];
            cpa16(sb + (kbo + (uint32_t)(r * PA + c4)) * 4, &Kp[(size_t)src * HD + c4]);
            cpa16(sb + (vbo + (uint32_t)(r * PA + c4)) * 4, &Vp[(size_t)src * HD + c4]);
        }
        CP_COMMIT();
    };
    issue(0, 0);
    issue(1, 1);

    // Q A-frags direct from gmem (overlaps the cp.async flights above).
    // Slot order for hw-k remap: a0=Q[row][2t], a1=Q[row+8][2t],
    // a2=Q[row][2t+1], a3=Q[row+8][2t+1].
    uint32_t q[2][8][4];
    #pragma unroll
    for (int m = 0; m < 2; ++m) {
        const int row = q0 + r0 + m * 16 + g;
        #pragma unroll
        for (int n = 0; n < 8; ++n) {
            float2 f0 = *(const float2*)&Qp[(size_t)row * HD + n * 8 + 2 * t];
            float2 f1 = *(const float2*)&Qp[(size_t)(row + 8) * HD + n * 8 + 2 * t];
            q[m][n][0] = __float_as_uint(f0.x);
            q[m][n][1] = __float_as_uint(f1.x);
            q[m][n][2] = __float_as_uint(f0.y);
            q[m][n][3] = __float_as_uint(f1.y);
        }
    }

    float o[2][8][4] = {};
    float rs[2][2] = {};
    float p[2][8][4];

    for (int it = 0; it < nt; ++it) {
        CP_WAIT(1);
        __syncthreads();

        const float* Kb = sm + ((it & 1) ? KB1 : KB0);
        const float* Vb = sm + ((it & 1) ? VB1 : VB0);

        // S = Q K^T: register A-frags; B = contiguous float2 K loads
        #pragma unroll
        for (int m = 0; m < 2; ++m)
            #pragma unroll
            for (int n = 0; n < 8; ++n)
                #pragma unroll
                for (int j = 0; j < 4; ++j) p[m][n][j] = 0.f;
        #pragma unroll
        for (int kk = 0; kk < 8; ++kk) {
            #pragma unroll
            for (int n = 0; n < 8; ++n) {
                float2 kv = *(const float2*)&Kb[(n * 8 + g) * PA + kk * 8 + 2 * t];
                uint32_t bb[2] = { __float_as_uint(kv.x), __float_as_uint(kv.y) };
                mma8(p[0][n], q[0][kk], bb);
                mma8(p[1][n], q[1][kk], bb);
            }
        }

        exp_tile(p, it * 64, nb, rs, t);
        pv_tile(o, p, Vb, g, t);

        __syncthreads();
        if (it + 2 < nt) issue(it + 2, it & 1);
        else CP_COMMIT();
    }

    #pragma unroll
    for (int m = 0; m < 2; ++m)
        #pragma unroll
        for (int j = 0; j < 2; ++j) {
            rs[m][j] += __shfl_xor_sync(0xffffffffu, rs[m][j], 1);
            rs[m][j] += __shfl_xor_sync(0xffffffffu, rs[m][j], 2);
        }

    #pragma unroll
    for (int m = 0; m < 2; ++m) {
        const float inv0 = 1.0f / rs[m][0], inv1 = 1.0f / rs[m][1];
        const int row = q0 + r0 + m * 16 + g;
        #pragma unroll
        for (int n = 0; n < 8; ++n) {
            int col = n * 8 + t * 2;
            size_t base0 = ((size_t)(b * SS + row)) * DD + h * HD + col;
            size_t base1 = ((size_t)(b * SS + row + 8)) * DD + h * HD + col;
            *(float2*)&g_C[base0] = make_float2(cvtf(o[m][n][0] * inv0), cvtf(o[m][n][1] * inv0));
            *(float2*)&g_C[base1] = make_float2(cvtf(o[m][n][2] * inv1), cvtf(o[m][n][3] * inv1));
        }
    }
}

// ============================================================================
// Kernel 3: out-proj Y = C @ Wo^T + bo (R12-identical). grid (8, 64),
// 128 threads, block 128x128, warp 64x64, double-buffered k-chunks of 32.
// ============================================================================
#define PO 36
#define OB_STRIDE (2 * 128 * PO)

__global__ __launch_bounds__(128, 2) void outproj_mma(
    const float* __restrict__ bo, float* __restrict__ y)
{
    extern __shared__ float sm[];
    const uint32_t sb = smem_u32(sm);

    const int n0 = blockIdx.x * 128;
    const int m0 = blockIdx.y * 128;
    const int tid = threadIdx.x, wid = tid >> 5, lane = tid & 31;
    const int g = lane >> 2, t = lane & 3;
    const int wr = wid & 1, wc = wid >> 1;
    const int r0 = wr * 64, c0 = wc * 64;

    auto issue = [&](int ch, int buf) {
        const uint32_t bofs = (uint32_t)(buf * OB_STRIDE);
        for (int i = tid; i < 128 * 8; i += 128) {
            int r = i >> 3, c4 = (i & 7) << 2;
            cpa16(sb + (bofs + (uint32_t)(r * PO + c4)) * 4,
                  &g_C[(size_t)(m0 + r) * DD + ch * 32 + c4]);
            cpa16(sb + (bofs + (uint32_t)(128 * PO + r * PO + c4)) * 4,
                  &g_Wo[(size_t)(n0 + r) * DD + ch * 32 + c4]);
        }
        CP_COMMIT();
    };
    issue(0, 0);
    issue(1, 1);

    float acc[4][8][4] = {};
    for (int ch = 0; ch < 32; ++ch) {
        CP_WAIT(1);
        __syncthreads();
        const float* Cs = sm + (ch & 1) * OB_STRIDE;
        const float* Ws = Cs + 128 * PO;
        #pragma unroll
        for (int kk = 0; kk < 4; ++kk) {
            uint32_t a_[4][4];
            #pragma unroll
            for (int m = 0; m < 4; ++m)
                lda(a_[m], Cs, PO, r0 + m * 16, kk * 8, g, t);
            #pragma unroll
            for (int n = 0; n < 8; ++n) {
                uint32_t bb[2];
                ldb_nk(bb, Ws, PO, c0 + n * 8, kk * 8, g, t);
                #pragma unroll
                for (int m = 0; m < 4; ++m)
                    mma8(acc[m][n], a_[m], bb);
            }
        }
        __syncthreads();
        if (ch + 2 < 32) issue(ch + 2, ch & 1);
        else CP_COMMIT();
    }

    #pragma unroll
    for (int m = 0; m < 4; ++m) {
        #pragma unroll
        for (int n = 0; n < 8; ++n) {
            int col = c0 + n * 8 + t * 2;
            float b0 = bo[n0 + col], b1 = bo[n0 + col + 1];
            int row = m0 + r0 + m * 16 + g;
            size_t base0 = (size_t)row * DD + n0 + col;
            size_t base1 = (size_t)(row + 8) * DD + n0 + col;
            *(float2*)&y[base0] = make_float2(acc[m][n][0] + b0, acc[m][n][1] + b1);
            *(float2*)&y[base1] = make_float2(acc[m][n][2] + b0, acc[m][n][3] + b1);
        }
    }
}

// ============================================================================
extern "C" void kernel_launch(void* const* d_in, const int* in_sizes, int n_in,
                              void* d_out, int out_size)
{
    const float* x  = (const float*)d_in[0];
    const int* mk   = (const int*)d_in[1];
    const float* Wq = (const float*)d_in[2];
    const float* bq = (const float*)d_in[3];
    const float* Wk = (const float*)d_in[4];
    const float* bk = (const float*)d_in[5];
    const float* Wv = (const float*)d_in[6];
    const float* bv = (const float*)d_in[7];
    const float* Wo = (const float*)d_in[8];
    const float* bo = (const float*)d_in[9];
    float* y = (float*)d_out;

    const int smem_proj = PRJ_SMEM_F * 4;     // ~88 KB
    const int smem_attn = ATTN_F * 4;         // ~71.7 KB -> 2 CTAs/SM
    const int smem_out  = 2 * OB_STRIDE * 4;  // 72 KB -> 2 CTAs/SM
    cudaFuncSetAttribute(proj_mma, cudaFuncAttributeMaxDynamicSharedMemorySize, smem_proj);
    cudaFuncSetAttribute(attn_mma, cudaFuncAttributeMaxDynamicSharedMemorySize, smem_attn);
    cudaFuncSetAttribute(outproj_mma, cudaFuncAttributeMaxDynamicSharedMemorySize, smem_out);

    round_wo<<<DD * DD / 1024, 256>>>(Wo);
    build_idx<<<BB, SS>>>(mk);
    proj_mma<<<dim3(SS / 128, HH, BB), 512, smem_proj>>>(x, Wq, bq, Wk, bk, Wv, bv);
    attn_mma<<<dim3(SS / 128, HH, BB), 128, smem_attn>>>();
    outproj_mma<<<dim3(DD / 128, BB * SS / 128), 128, smem_out>>>(bo, y);
}